// round 1
// baseline (speedup 1.0000x reference)
#include <cuda_runtime.h>
#include <math.h>

#define BATCH 4
#define NTOK 2048
#define DMODEL 1024
#define NHEAD 16
#define HDIM 64
#define MROWS (BATCH * NTOK)   // 8192

// Scratch (device globals: no allocations allowed)
__device__ float g_q[BATCH * NHEAD * NTOK * HDIM];     // [B,H,N,hd]
__device__ float g_k[BATCH * NHEAD * NTOK * HDIM];
__device__ float g_v[BATCH * NHEAD * NTOK * HDIM];
__device__ float g_attn[MROWS * DMODEL];               // [B*N, D]

// ---------------------------------------------------------------------------
// GEMM: C = (A[8192,1024] @ W[1024,1024] + bias) * scale
// head_layout=1 -> write C in [B,H,N,hd] layout (for q/k/v); else [M,1024].
// 64x64 tile, BK=16, 256 threads, 4x4 micro-tile per thread.
// ---------------------------------------------------------------------------
__global__ __launch_bounds__(256)
void gemm_bias_kernel(const float* __restrict__ A,
                      const float* __restrict__ W,
                      const float* __restrict__ bias,
                      float* __restrict__ C,
                      int head_layout, float scale)
{
    __shared__ float As[16 * 64];   // As[k][m] (transposed)
    __shared__ float Ws[16 * 64];   // Ws[k][n]

    const int tx = threadIdx.x;     // 0..15
    const int ty = threadIdx.y;     // 0..15
    const int t  = ty * 16 + tx;
    const int m0 = blockIdx.y * 64;
    const int n0 = blockIdx.x * 64;

    const int lrow = t >> 2;        // A-load: row within tile 0..63
    const int lk4  = t & 3;         // A-load: which float4 of the 16-wide K slab
    const int wk   = t >> 4;        // W-load: k row 0..15
    const int wc4  = t & 15;        // W-load: which float4 of 64 cols

    float acc[4][4] = {};

    for (int k0 = 0; k0 < 1024; k0 += 16) {
        float4 av = *(const float4*)&A[(size_t)(m0 + lrow) * 1024 + k0 + lk4 * 4];
        float4 wv = *(const float4*)&W[(size_t)(k0 + wk) * 1024 + n0 + wc4 * 4];
        __syncthreads();
        As[(lk4 * 4 + 0) * 64 + lrow] = av.x;
        As[(lk4 * 4 + 1) * 64 + lrow] = av.y;
        As[(lk4 * 4 + 2) * 64 + lrow] = av.z;
        As[(lk4 * 4 + 3) * 64 + lrow] = av.w;
        *(float4*)&Ws[wk * 64 + wc4 * 4] = wv;
        __syncthreads();
#pragma unroll
        for (int kk = 0; kk < 16; kk++) {
            float4 a = *(const float4*)&As[kk * 64 + ty * 4];
            float4 b = *(const float4*)&Ws[kk * 64 + tx * 4];
            float rm[4] = {a.x, a.y, a.z, a.w};
            float rn[4] = {b.x, b.y, b.z, b.w};
#pragma unroll
            for (int i = 0; i < 4; i++)
#pragma unroll
                for (int j = 0; j < 4; j++)
                    acc[i][j] += rm[i] * rn[j];
        }
    }

    const int c = n0 + tx * 4;
    float4 bv = *(const float4*)&bias[c];
#pragma unroll
    for (int r = 0; r < 4; r++) {
        const int m = m0 + ty * 4 + r;
        float4 o;
        o.x = (acc[r][0] + bv.x) * scale;
        o.y = (acc[r][1] + bv.y) * scale;
        o.z = (acc[r][2] + bv.z) * scale;
        o.w = (acc[r][3] + bv.w) * scale;
        if (head_layout) {
            const int b_  = m >> 11;           // m / 2048
            const int n_  = m & 2047;
            const int h_  = c >> 6;            // c / 64
            const int hd_ = c & 63;
            *(float4*)&C[(((size_t)(b_ * NHEAD + h_) * NTOK) + n_) * HDIM + hd_] = o;
        } else {
            *(float4*)&C[(size_t)m * 1024 + c] = o;
        }
    }
}

// ---------------------------------------------------------------------------
// Flash attention (causal), fp32. One CTA = one (b,h) and 64 query rows.
// Online softmax; K smem buffer is reused for P after S is computed.
// ---------------------------------------------------------------------------
__global__ __launch_bounds__(256)
void attn_kernel(const float* __restrict__ q,
                 const float* __restrict__ k,
                 const float* __restrict__ v,
                 float* __restrict__ o)
{
    __shared__ float Qs[64 * 64];    // Qs[d][i] (transposed)
    __shared__ float KPs[64 * 64];   // K transposed [d][j], then reused as P [j][i]
    __shared__ float Vs[64 * 64];    // Vs[j][d]

    const int tx = threadIdx.x;      // 0..15
    const int ty = threadIdx.y;      // 0..15
    const int t  = ty * 16 + tx;
    const int qt = blockIdx.x;       // query tile 0..31
    const int bh = blockIdx.y;       // 0..63
    const int q0 = qt * 64;

    const float* qp = q + (size_t)bh * NTOK * HDIM;
    const float* kp = k + (size_t)bh * NTOK * HDIM;
    const float* vp = v + (size_t)bh * NTOK * HDIM;

    // Load Q tile transposed (Q already scaled by 1/sqrt(hd) at projection)
#pragma unroll
    for (int rr = 0; rr < 4; rr++) {
        const int j  = (t >> 4) + rr * 16;   // token 0..63
        const int d4 = t & 15;
        float4 qv = *(const float4*)&qp[(size_t)(q0 + j) * HDIM + d4 * 4];
        Qs[(d4 * 4 + 0) * 64 + j] = qv.x;
        Qs[(d4 * 4 + 1) * 64 + j] = qv.y;
        Qs[(d4 * 4 + 2) * 64 + j] = qv.z;
        Qs[(d4 * 4 + 3) * 64 + j] = qv.w;
    }

    float acc[4][4] = {};
    float mrow[4] = {-INFINITY, -INFINITY, -INFINITY, -INFINITY};
    float lrow[4] = {0.f, 0.f, 0.f, 0.f};

    for (int kt = 0; kt <= qt; kt++) {
        const int k0 = kt * 64;
        __syncthreads();   // previous P/V reads done; also makes Qs visible on first iter... (store below)
        // Load K (transposed) and V (natural)
#pragma unroll
        for (int rr = 0; rr < 4; rr++) {
            const int j  = (t >> 4) + rr * 16;
            const int d4 = t & 15;
            float4 kv = *(const float4*)&kp[(size_t)(k0 + j) * HDIM + d4 * 4];
            KPs[(d4 * 4 + 0) * 64 + j] = kv.x;
            KPs[(d4 * 4 + 1) * 64 + j] = kv.y;
            KPs[(d4 * 4 + 2) * 64 + j] = kv.z;
            KPs[(d4 * 4 + 3) * 64 + j] = kv.w;
            float4 vv = *(const float4*)&vp[(size_t)(k0 + j) * HDIM + d4 * 4];
            *(float4*)&Vs[j * 64 + d4 * 4] = vv;
        }
        __syncthreads();

        // S = Q K^T  (rows i = ty*4+r, cols j = tx*4+u)
        float s[4][4] = {};
#pragma unroll
        for (int d = 0; d < 64; d++) {
            float4 a = *(const float4*)&Qs[d * 64 + ty * 4];
            float4 b = *(const float4*)&KPs[d * 64 + tx * 4];
            float rm[4] = {a.x, a.y, a.z, a.w};
            float rn[4] = {b.x, b.y, b.z, b.w};
#pragma unroll
            for (int i = 0; i < 4; i++)
#pragma unroll
                for (int j = 0; j < 4; j++)
                    s[i][j] += rm[i] * rn[j];
        }

        // Causal mask (only the diagonal tile needs it)
        if (kt == qt) {
#pragma unroll
            for (int r = 0; r < 4; r++)
#pragma unroll
                for (int u = 0; u < 4; u++)
                    if (k0 + tx * 4 + u > q0 + ty * 4 + r) s[r][u] = -1e30f;
        }

        // Online softmax (row reduction across the 16 tx lanes of this warp half)
#pragma unroll
        for (int r = 0; r < 4; r++) {
            float mx = fmaxf(fmaxf(s[r][0], s[r][1]), fmaxf(s[r][2], s[r][3]));
#pragma unroll
            for (int off = 1; off < 16; off <<= 1)
                mx = fmaxf(mx, __shfl_xor_sync(0xffffffffu, mx, off));
            const float nm = fmaxf(mrow[r], mx);
            const float corr = __expf(mrow[r] - nm);
            float ps = 0.f;
#pragma unroll
            for (int u = 0; u < 4; u++) {
                s[r][u] = __expf(s[r][u] - nm);
                ps += s[r][u];
            }
#pragma unroll
            for (int off = 1; off < 16; off <<= 1)
                ps += __shfl_xor_sync(0xffffffffu, ps, off);
            lrow[r] = lrow[r] * corr + ps;
#pragma unroll
            for (int u = 0; u < 4; u++) acc[r][u] *= corr;
            mrow[r] = nm;
        }

        __syncthreads();   // everyone done reading K from KPs
        // Write P transposed into KPs: P[j][i]
#pragma unroll
        for (int r = 0; r < 4; r++)
#pragma unroll
            for (int u = 0; u < 4; u++)
                KPs[(tx * 4 + u) * 64 + ty * 4 + r] = s[r][u];
        __syncthreads();

        // O += P V   (rows i = ty*4+r, hd cols = tx*4+u)
#pragma unroll
        for (int j = 0; j < 64; j++) {
            float4 a = *(const float4*)&KPs[j * 64 + ty * 4];
            float4 b = *(const float4*)&Vs[j * 64 + tx * 4];
            float rm[4] = {a.x, a.y, a.z, a.w};
            float rn[4] = {b.x, b.y, b.z, b.w};
#pragma unroll
            for (int i = 0; i < 4; i++)
#pragma unroll
                for (int jj = 0; jj < 4; jj++)
                    acc[i][jj] += rm[i] * rn[jj];
        }
    }

    // Epilogue: normalize and write to [B*N, D] layout for the output projection
    const int b_ = bh >> 4;
    const int h_ = bh & 15;
#pragma unroll
    for (int r = 0; r < 4; r++) {
        const float inv = 1.f / lrow[r];
        const int n_ = q0 + ty * 4 + r;
        float4 ov;
        ov.x = acc[r][0] * inv;
        ov.y = acc[r][1] * inv;
        ov.z = acc[r][2] * inv;
        ov.w = acc[r][3] * inv;
        *(float4*)&o[((size_t)(b_ * NTOK + n_)) * DMODEL + h_ * HDIM + tx * 4] = ov;
    }
}

// ---------------------------------------------------------------------------
extern "C" void kernel_launch(void* const* d_in, const int* in_sizes, int n_in,
                              void* d_out, int out_size)
{
    const float* x  = (const float*)d_in[0];
    const float* Wq = (const float*)d_in[1];
    const float* bq = (const float*)d_in[2];
    const float* Wk = (const float*)d_in[3];
    const float* bk = (const float*)d_in[4];
    const float* Wv = (const float*)d_in[5];
    const float* bv = (const float*)d_in[6];
    const float* Wo = (const float*)d_in[7];
    const float* bo = (const float*)d_in[8];
    float* out = (float*)d_out;

    float *gq, *gk, *gv, *ga;
    cudaGetSymbolAddress((void**)&gq, g_q);
    cudaGetSymbolAddress((void**)&gk, g_k);
    cudaGetSymbolAddress((void**)&gv, g_v);
    cudaGetSymbolAddress((void**)&ga, g_attn);

    dim3 blk(16, 16);
    dim3 ggemm(DMODEL / 64, MROWS / 64);   // (16, 128)

    const float qscale = 0.125f;  // 1/sqrt(64)
    gemm_bias_kernel<<<ggemm, blk>>>(x, Wq, bq, gq, 1, qscale);
    gemm_bias_kernel<<<ggemm, blk>>>(x, Wk, bk, gk, 1, 1.f);
    gemm_bias_kernel<<<ggemm, blk>>>(x, Wv, bv, gv, 1, 1.f);

    dim3 gattn(NTOK / 64, BATCH * NHEAD);  // (32, 64)
    attn_kernel<<<gattn, blk>>>(gq, gk, gv, ga);

    gemm_bias_kernel<<<ggemm, blk>>>(ga, Wo, bo, out, 0, 1.f);
}

// round 2
// speedup vs baseline: 1.4988x; 1.4988x over previous
#include <cuda_runtime.h>
#include <math.h>
#include <stdint.h>

#define BATCH 4
#define NTOK 2048
#define DMODEL 1024
#define NHEAD 16
#define HDIM 64
#define MROWS (BATCH * NTOK)   // 8192

// Scratch (device globals: no allocations allowed)
__device__ float g_q[BATCH * NHEAD * NTOK * HDIM];     // [B,H,N,hd]
__device__ float g_k[BATCH * NHEAD * NTOK * HDIM];
__device__ float g_v[BATCH * NHEAD * NTOK * HDIM];
__device__ float g_attn[MROWS * DMODEL];               // [B*N, D]

__device__ __forceinline__ uint32_t f2tf32(float f) {
    uint32_t u;
    asm("cvt.rna.tf32.f32 %0, %1;" : "=r"(u) : "f"(f));
    return u;
}

// ---------------------------------------------------------------------------
// TF32 tensor-core GEMM: C = (A[8192,1024] @ W[1024,1024] + bias) * scale
// 128x128 CTA tile, BK=16, 256 threads = 8 warps, warp tile 64x32 (2x4 grid),
// mma.sync.m16n8k8.tf32. head_layout=1 -> scatter into [B,H,N,hd].
// ---------------------------------------------------------------------------
#define AS_STRIDE 17     // 16 + 1 pad (uint32 units)
#define BS_STRIDE 132    // 128 + 4 pad

__global__ __launch_bounds__(256)
void gemm_tf32_kernel(const float* __restrict__ A,
                      const float* __restrict__ W,
                      const float* __restrict__ bias,
                      float* __restrict__ C,
                      int head_layout, float scale)
{
    __shared__ uint32_t As[128 * AS_STRIDE];   // [m][k], tf32 bits
    __shared__ uint32_t Bs[16 * BS_STRIDE];    // [k][n], tf32 bits

    const int t     = threadIdx.x;
    const int warp  = t >> 5;
    const int lane  = t & 31;
    const int g     = lane >> 2;    // groupID 0..7
    const int tid4  = lane & 3;     // 0..3
    const int wm0   = (warp >> 2) * 64;   // warp row origin in tile (0/64)
    const int wn0   = (warp & 3) * 32;    // warp col origin (0/32/64/96)

    const int m0 = blockIdx.y * 128;
    const int n0 = blockIdx.x * 128;

    // global-load coordinates
    const int ar0 = t >> 2;          // A rows t/4 and t/4+64
    const int ac4 = t & 3;           // A float4 col within 16-wide slab
    const int br0 = t >> 5;          // B rows t/32 and t/32+8
    const int bc4 = t & 31;          // B float4 col within 128-wide slab

    float acc[4][4][4] = {};

    for (int k0 = 0; k0 < 1024; k0 += 16) {
        float4 av0 = *(const float4*)&A[(size_t)(m0 + ar0) * 1024 + k0 + ac4 * 4];
        float4 av1 = *(const float4*)&A[(size_t)(m0 + ar0 + 64) * 1024 + k0 + ac4 * 4];
        float4 bv0 = *(const float4*)&W[(size_t)(k0 + br0) * 1024 + n0 + bc4 * 4];
        float4 bv1 = *(const float4*)&W[(size_t)(k0 + br0 + 8) * 1024 + n0 + bc4 * 4];
        __syncthreads();
        {
            uint32_t* p = &As[ar0 * AS_STRIDE + ac4 * 4];
            p[0] = f2tf32(av0.x); p[1] = f2tf32(av0.y);
            p[2] = f2tf32(av0.z); p[3] = f2tf32(av0.w);
            uint32_t* p2 = &As[(ar0 + 64) * AS_STRIDE + ac4 * 4];
            p2[0] = f2tf32(av1.x); p2[1] = f2tf32(av1.y);
            p2[2] = f2tf32(av1.z); p2[3] = f2tf32(av1.w);
            uint32_t* q = &Bs[br0 * BS_STRIDE + bc4 * 4];
            q[0] = f2tf32(bv0.x); q[1] = f2tf32(bv0.y);
            q[2] = f2tf32(bv0.z); q[3] = f2tf32(bv0.w);
            uint32_t* q2 = &Bs[(br0 + 8) * BS_STRIDE + bc4 * 4];
            q2[0] = f2tf32(bv1.x); q2[1] = f2tf32(bv1.y);
            q2[2] = f2tf32(bv1.z); q2[3] = f2tf32(bv1.w);
        }
        __syncthreads();

#pragma unroll
        for (int ks = 0; ks < 16; ks += 8) {
            uint32_t afr[4][4];
            uint32_t bfr[4][2];
#pragma unroll
            for (int mi = 0; mi < 4; mi++) {
                const int r0 = wm0 + mi * 16 + g;
                afr[mi][0] = As[r0 * AS_STRIDE + ks + tid4];
                afr[mi][1] = As[(r0 + 8) * AS_STRIDE + ks + tid4];
                afr[mi][2] = As[r0 * AS_STRIDE + ks + 4 + tid4];
                afr[mi][3] = As[(r0 + 8) * AS_STRIDE + ks + 4 + tid4];
            }
#pragma unroll
            for (int ni = 0; ni < 4; ni++) {
                const int c = wn0 + ni * 8 + g;
                bfr[ni][0] = Bs[(ks + tid4) * BS_STRIDE + c];
                bfr[ni][1] = Bs[(ks + 4 + tid4) * BS_STRIDE + c];
            }
#pragma unroll
            for (int mi = 0; mi < 4; mi++)
#pragma unroll
                for (int ni = 0; ni < 4; ni++) {
                    asm volatile(
                        "mma.sync.aligned.m16n8k8.row.col.f32.tf32.tf32.f32 "
                        "{%0,%1,%2,%3}, {%4,%5,%6,%7}, {%8,%9}, {%0,%1,%2,%3};\n"
                        : "+f"(acc[mi][ni][0]), "+f"(acc[mi][ni][1]),
                          "+f"(acc[mi][ni][2]), "+f"(acc[mi][ni][3])
                        : "r"(afr[mi][0]), "r"(afr[mi][1]),
                          "r"(afr[mi][2]), "r"(afr[mi][3]),
                          "r"(bfr[ni][0]), "r"(bfr[ni][1]));
                }
        }
    }

    // Epilogue. c0,c1: (g, tid4*2 .. +1); c2,c3: (g+8, same cols)
#pragma unroll
    for (int ni = 0; ni < 4; ni++) {
        const int c = n0 + wn0 + ni * 8 + tid4 * 2;
        const float b0 = bias[c], b1 = bias[c + 1];
#pragma unroll
        for (int mi = 0; mi < 4; mi++) {
#pragma unroll
            for (int half = 0; half < 2; half++) {
                const int m = m0 + wm0 + mi * 16 + g + half * 8;
                float2 o;
                o.x = (acc[mi][ni][half * 2 + 0] + b0) * scale;
                o.y = (acc[mi][ni][half * 2 + 1] + b1) * scale;
                if (head_layout) {
                    const int b_  = m >> 11;
                    const int n_  = m & 2047;
                    const int h_  = c >> 6;
                    const int hd_ = c & 63;
                    *(float2*)&C[(((size_t)(b_ * NHEAD + h_) * NTOK) + n_) * HDIM + hd_] = o;
                } else {
                    *(float2*)&C[(size_t)m * 1024 + c] = o;
                }
            }
        }
    }
}

// ---------------------------------------------------------------------------
// Flash attention (causal), fp32. One CTA = one (b,h) and 64 query rows.
// (unchanged from R0 — converted to tensor cores next round)
// ---------------------------------------------------------------------------
__global__ __launch_bounds__(256)
void attn_kernel(const float* __restrict__ q,
                 const float* __restrict__ k,
                 const float* __restrict__ v,
                 float* __restrict__ o)
{
    __shared__ float Qs[64 * 64];    // Qs[d][i]
    __shared__ float KPs[64 * 64];   // K^T [d][j], reused as P [j][i]
    __shared__ float Vs[64 * 64];    // Vs[j][d]

    const int tx = threadIdx.x;
    const int ty = threadIdx.y;
    const int t  = ty * 16 + tx;
    const int qt = blockIdx.x;
    const int bh = blockIdx.y;
    const int q0 = qt * 64;

    const float* qp = q + (size_t)bh * NTOK * HDIM;
    const float* kp = k + (size_t)bh * NTOK * HDIM;
    const float* vp = v + (size_t)bh * NTOK * HDIM;

#pragma unroll
    for (int rr = 0; rr < 4; rr++) {
        const int j  = (t >> 4) + rr * 16;
        const int d4 = t & 15;
        float4 qv = *(const float4*)&qp[(size_t)(q0 + j) * HDIM + d4 * 4];
        Qs[(d4 * 4 + 0) * 64 + j] = qv.x;
        Qs[(d4 * 4 + 1) * 64 + j] = qv.y;
        Qs[(d4 * 4 + 2) * 64 + j] = qv.z;
        Qs[(d4 * 4 + 3) * 64 + j] = qv.w;
    }

    float acc[4][4] = {};
    float mrow[4] = {-INFINITY, -INFINITY, -INFINITY, -INFINITY};
    float lrow[4] = {0.f, 0.f, 0.f, 0.f};

    for (int kt = 0; kt <= qt; kt++) {
        const int k0 = kt * 64;
        __syncthreads();
#pragma unroll
        for (int rr = 0; rr < 4; rr++) {
            const int j  = (t >> 4) + rr * 16;
            const int d4 = t & 15;
            float4 kv = *(const float4*)&kp[(size_t)(k0 + j) * HDIM + d4 * 4];
            KPs[(d4 * 4 + 0) * 64 + j] = kv.x;
            KPs[(d4 * 4 + 1) * 64 + j] = kv.y;
            KPs[(d4 * 4 + 2) * 64 + j] = kv.z;
            KPs[(d4 * 4 + 3) * 64 + j] = kv.w;
            float4 vv = *(const float4*)&vp[(size_t)(k0 + j) * HDIM + d4 * 4];
            *(float4*)&Vs[j * 64 + d4 * 4] = vv;
        }
        __syncthreads();

        float s[4][4] = {};
#pragma unroll
        for (int d = 0; d < 64; d++) {
            float4 a = *(const float4*)&Qs[d * 64 + ty * 4];
            float4 b = *(const float4*)&KPs[d * 64 + tx * 4];
            float rm[4] = {a.x, a.y, a.z, a.w};
            float rn[4] = {b.x, b.y, b.z, b.w};
#pragma unroll
            for (int i = 0; i < 4; i++)
#pragma unroll
                for (int j = 0; j < 4; j++)
                    s[i][j] += rm[i] * rn[j];
        }

        if (kt == qt) {
#pragma unroll
            for (int r = 0; r < 4; r++)
#pragma unroll
                for (int u = 0; u < 4; u++)
                    if (k0 + tx * 4 + u > q0 + ty * 4 + r) s[r][u] = -1e30f;
        }

#pragma unroll
        for (int r = 0; r < 4; r++) {
            float mx = fmaxf(fmaxf(s[r][0], s[r][1]), fmaxf(s[r][2], s[r][3]));
#pragma unroll
            for (int off = 1; off < 16; off <<= 1)
                mx = fmaxf(mx, __shfl_xor_sync(0xffffffffu, mx, off));
            const float nm = fmaxf(mrow[r], mx);
            const float corr = __expf(mrow[r] - nm);
            float ps = 0.f;
#pragma unroll
            for (int u = 0; u < 4; u++) {
                s[r][u] = __expf(s[r][u] - nm);
                ps += s[r][u];
            }
#pragma unroll
            for (int off = 1; off < 16; off <<= 1)
                ps += __shfl_xor_sync(0xffffffffu, ps, off);
            lrow[r] = lrow[r] * corr + ps;
#pragma unroll
            for (int u = 0; u < 4; u++) acc[r][u] *= corr;
            mrow[r] = nm;
        }

        __syncthreads();
#pragma unroll
        for (int r = 0; r < 4; r++)
#pragma unroll
            for (int u = 0; u < 4; u++)
                KPs[(tx * 4 + u) * 64 + ty * 4 + r] = s[r][u];
        __syncthreads();

#pragma unroll
        for (int j = 0; j < 64; j++) {
            float4 a = *(const float4*)&KPs[j * 64 + ty * 4];
            float4 b = *(const float4*)&Vs[j * 64 + tx * 4];
            float rm[4] = {a.x, a.y, a.z, a.w};
            float rn[4] = {b.x, b.y, b.z, b.w};
#pragma unroll
            for (int i = 0; i < 4; i++)
#pragma unroll
                for (int jj = 0; jj < 4; jj++)
                    acc[i][jj] += rm[i] * rn[jj];
        }
    }

    const int b_ = bh >> 4;
    const int h_ = bh & 15;
#pragma unroll
    for (int r = 0; r < 4; r++) {
        const float inv = 1.f / lrow[r];
        const int n_ = q0 + ty * 4 + r;
        float4 ov;
        ov.x = acc[r][0] * inv;
        ov.y = acc[r][1] * inv;
        ov.z = acc[r][2] * inv;
        ov.w = acc[r][3] * inv;
        *(float4*)&o[((size_t)(b_ * NTOK + n_)) * DMODEL + h_ * HDIM + tx * 4] = ov;
    }
}

// ---------------------------------------------------------------------------
extern "C" void kernel_launch(void* const* d_in, const int* in_sizes, int n_in,
                              void* d_out, int out_size)
{
    const float* x  = (const float*)d_in[0];
    const float* Wq = (const float*)d_in[1];
    const float* bq = (const float*)d_in[2];
    const float* Wk = (const float*)d_in[3];
    const float* bk = (const float*)d_in[4];
    const float* Wv = (const float*)d_in[5];
    const float* bv = (const float*)d_in[6];
    const float* Wo = (const float*)d_in[7];
    const float* bo = (const float*)d_in[8];
    float* out = (float*)d_out;

    float *gq, *gk, *gv, *ga;
    cudaGetSymbolAddress((void**)&gq, g_q);
    cudaGetSymbolAddress((void**)&gk, g_k);
    cudaGetSymbolAddress((void**)&gv, g_v);
    cudaGetSymbolAddress((void**)&ga, g_attn);

    dim3 ggemm(DMODEL / 128, MROWS / 128);   // (8, 64)

    const float qscale = 0.125f;  // 1/sqrt(64)
    gemm_tf32_kernel<<<ggemm, 256>>>(x, Wq, bq, gq, 1, qscale);
    gemm_tf32_kernel<<<ggemm, 256>>>(x, Wk, bk, gk, 1, 1.f);
    gemm_tf32_kernel<<<ggemm, 256>>>(x, Wv, bv, gv, 1, 1.f);

    dim3 blk16(16, 16);
    dim3 gattn(NTOK / 64, BATCH * NHEAD);    // (32, 64)
    attn_kernel<<<gattn, blk16>>>(gq, gk, gv, ga);

    gemm_tf32_kernel<<<ggemm, 256>>>(ga, Wo, bo, out, 0, 1.f);
}

// round 3
// speedup vs baseline: 2.8670x; 1.9128x over previous
#include <cuda_runtime.h>
#include <math.h>
#include <stdint.h>

#define BATCH 4
#define NTOK 2048
#define DMODEL 1024
#define NHEAD 16
#define HDIM 64
#define MROWS (BATCH * NTOK)   // 8192

__device__ float g_q[BATCH * NHEAD * NTOK * HDIM];     // [B,H,N,hd]
__device__ float g_k[BATCH * NHEAD * NTOK * HDIM];
__device__ float g_v[BATCH * NHEAD * NTOK * HDIM];
__device__ float g_attn[MROWS * DMODEL];               // [B*N, D]

__device__ __forceinline__ uint32_t f2tf32(float f) {
    uint32_t u;
    asm("cvt.rna.tf32.f32 %0, %1;" : "=r"(u) : "f"(f));
    return u;
}

__device__ __forceinline__ void mma_tf32(float c[4],
                                         uint32_t a0, uint32_t a1, uint32_t a2, uint32_t a3,
                                         uint32_t b0, uint32_t b1) {
    asm volatile(
        "mma.sync.aligned.m16n8k8.row.col.f32.tf32.tf32.f32 "
        "{%0,%1,%2,%3}, {%4,%5,%6,%7}, {%8,%9}, {%0,%1,%2,%3};\n"
        : "+f"(c[0]), "+f"(c[1]), "+f"(c[2]), "+f"(c[3])
        : "r"(a0), "r"(a1), "r"(a2), "r"(a3), "r"(b0), "r"(b1));
}

// ---------------------------------------------------------------------------
// TF32 tensor-core GEMM (unchanged from R1): C = (A @ W + bias) * scale
// ---------------------------------------------------------------------------
#define AS_STRIDE 17
#define BS_STRIDE 132

__global__ __launch_bounds__(256)
void gemm_tf32_kernel(const float* __restrict__ A,
                      const float* __restrict__ W,
                      const float* __restrict__ bias,
                      float* __restrict__ C,
                      int head_layout, float scale)
{
    __shared__ uint32_t As[128 * AS_STRIDE];
    __shared__ uint32_t Bs[16 * BS_STRIDE];

    const int t     = threadIdx.x;
    const int warp  = t >> 5;
    const int lane  = t & 31;
    const int g     = lane >> 2;
    const int tid4  = lane & 3;
    const int wm0   = (warp >> 2) * 64;
    const int wn0   = (warp & 3) * 32;

    const int m0 = blockIdx.y * 128;
    const int n0 = blockIdx.x * 128;

    const int ar0 = t >> 2;
    const int ac4 = t & 3;
    const int br0 = t >> 5;
    const int bc4 = t & 31;

    float acc[4][4][4] = {};

    for (int k0 = 0; k0 < 1024; k0 += 16) {
        float4 av0 = *(const float4*)&A[(size_t)(m0 + ar0) * 1024 + k0 + ac4 * 4];
        float4 av1 = *(const float4*)&A[(size_t)(m0 + ar0 + 64) * 1024 + k0 + ac4 * 4];
        float4 bv0 = *(const float4*)&W[(size_t)(k0 + br0) * 1024 + n0 + bc4 * 4];
        float4 bv1 = *(const float4*)&W[(size_t)(k0 + br0 + 8) * 1024 + n0 + bc4 * 4];
        __syncthreads();
        {
            uint32_t* p = &As[ar0 * AS_STRIDE + ac4 * 4];
            p[0] = f2tf32(av0.x); p[1] = f2tf32(av0.y);
            p[2] = f2tf32(av0.z); p[3] = f2tf32(av0.w);
            uint32_t* p2 = &As[(ar0 + 64) * AS_STRIDE + ac4 * 4];
            p2[0] = f2tf32(av1.x); p2[1] = f2tf32(av1.y);
            p2[2] = f2tf32(av1.z); p2[3] = f2tf32(av1.w);
            uint32_t* qq = &Bs[br0 * BS_STRIDE + bc4 * 4];
            qq[0] = f2tf32(bv0.x); qq[1] = f2tf32(bv0.y);
            qq[2] = f2tf32(bv0.z); qq[3] = f2tf32(bv0.w);
            uint32_t* q2 = &Bs[(br0 + 8) * BS_STRIDE + bc4 * 4];
            q2[0] = f2tf32(bv1.x); q2[1] = f2tf32(bv1.y);
            q2[2] = f2tf32(bv1.z); q2[3] = f2tf32(bv1.w);
        }
        __syncthreads();

#pragma unroll
        for (int ks = 0; ks < 16; ks += 8) {
            uint32_t afr[4][4];
            uint32_t bfr[4][2];
#pragma unroll
            for (int mi = 0; mi < 4; mi++) {
                const int r0 = wm0 + mi * 16 + g;
                afr[mi][0] = As[r0 * AS_STRIDE + ks + tid4];
                afr[mi][1] = As[(r0 + 8) * AS_STRIDE + ks + tid4];
                afr[mi][2] = As[r0 * AS_STRIDE + ks + 4 + tid4];
                afr[mi][3] = As[(r0 + 8) * AS_STRIDE + ks + 4 + tid4];
            }
#pragma unroll
            for (int ni = 0; ni < 4; ni++) {
                const int c = wn0 + ni * 8 + g;
                bfr[ni][0] = Bs[(ks + tid4) * BS_STRIDE + c];
                bfr[ni][1] = Bs[(ks + 4 + tid4) * BS_STRIDE + c];
            }
#pragma unroll
            for (int mi = 0; mi < 4; mi++)
#pragma unroll
                for (int ni = 0; ni < 4; ni++)
                    mma_tf32(acc[mi][ni], afr[mi][0], afr[mi][1], afr[mi][2], afr[mi][3],
                             bfr[ni][0], bfr[ni][1]);
        }
    }

#pragma unroll
    for (int ni = 0; ni < 4; ni++) {
        const int c = n0 + wn0 + ni * 8 + tid4 * 2;
        const float b0 = bias[c], b1 = bias[c + 1];
#pragma unroll
        for (int mi = 0; mi < 4; mi++) {
#pragma unroll
            for (int half = 0; half < 2; half++) {
                const int m = m0 + wm0 + mi * 16 + g + half * 8;
                float2 o;
                o.x = (acc[mi][ni][half * 2 + 0] + b0) * scale;
                o.y = (acc[mi][ni][half * 2 + 1] + b1) * scale;
                if (head_layout) {
                    const int b_  = m >> 11;
                    const int n_  = m & 2047;
                    const int h_  = c >> 6;
                    const int hd_ = c & 63;
                    *(float2*)&C[(((size_t)(b_ * NHEAD + h_) * NTOK) + n_) * HDIM + hd_] = o;
                } else {
                    *(float2*)&C[(size_t)m * 1024 + c] = o;
                }
            }
        }
    }
}

// ---------------------------------------------------------------------------
// Tensor-core flash attention (causal, tf32).
// BM=128 queries per CTA, BN=64 keys per iteration, 8 warps (warp = 16 rows).
// smem (dynamic, stride 68 for conflict-free fragment gathers):
//   Qs [128][68] | Ks [64][68] | Vs [64][68] | Ps [128][68]
// ---------------------------------------------------------------------------
#define AST 68
#define SM_Q 0
#define SM_K (128 * AST)
#define SM_V (SM_K + 64 * AST)
#define SM_P (SM_V + 64 * AST)
#define ATTN_SMEM_WORDS (SM_P + 128 * AST)

__global__ __launch_bounds__(256, 2)
void attn_tc_kernel(const float* __restrict__ q,
                    const float* __restrict__ k,
                    const float* __restrict__ v,
                    float* __restrict__ o)
{
    extern __shared__ uint32_t sm[];
    uint32_t* Qs = sm + SM_Q;
    uint32_t* Ks = sm + SM_K;
    uint32_t* Vs = sm + SM_V;
    uint32_t* Ps = sm + SM_P;

    const int t    = threadIdx.x;
    const int warp = t >> 5;
    const int lane = t & 31;
    const int g    = lane >> 2;
    const int t4   = lane & 3;
    const int wm0  = warp * 16;

    const int qt = blockIdx.x;
    const int bh = blockIdx.y;
    const int q0 = qt * 128;

    const float* qp = q + (size_t)bh * NTOK * HDIM;
    const float* kp = k + (size_t)bh * NTOK * HDIM;
    const float* vp = v + (size_t)bh * NTOK * HDIM;

    // Load Q tile [128][64] as tf32 (Q pre-scaled by 1/8 at projection)
#pragma unroll
    for (int i = 0; i < 8; i++) {
        const int idx = t + i * 256;
        const int row = idx >> 4;
        const int c4  = idx & 15;
        float4 qv = *(const float4*)&qp[(size_t)(q0 + row) * HDIM + c4 * 4];
        uint32_t* p = &Qs[row * AST + c4 * 4];
        p[0] = f2tf32(qv.x); p[1] = f2tf32(qv.y);
        p[2] = f2tf32(qv.z); p[3] = f2tf32(qv.w);
    }

    float acc[8][4] = {};
    float mrow[2] = {-INFINITY, -INFINITY};
    float lrow[2] = {0.f, 0.f};

    const int ktmax = 2 * qt + 1;
    for (int kt = 0; kt <= ktmax; kt++) {
        const int k0 = kt * 64;
        __syncthreads();
        // Load K,V tiles [64][64] as tf32
#pragma unroll
        for (int i = 0; i < 4; i++) {
            const int idx = t + i * 256;
            const int row = idx >> 4;
            const int c4  = idx & 15;
            float4 kv = *(const float4*)&kp[(size_t)(k0 + row) * HDIM + c4 * 4];
            uint32_t* pk = &Ks[row * AST + c4 * 4];
            pk[0] = f2tf32(kv.x); pk[1] = f2tf32(kv.y);
            pk[2] = f2tf32(kv.z); pk[3] = f2tf32(kv.w);
            float4 vv = *(const float4*)&vp[(size_t)(k0 + row) * HDIM + c4 * 4];
            uint32_t* pv = &Vs[row * AST + c4 * 4];
            pv[0] = f2tf32(vv.x); pv[1] = f2tf32(vv.y);
            pv[2] = f2tf32(vv.z); pv[3] = f2tf32(vv.w);
        }
        __syncthreads();

        // S = Q K^T : rows wm0+g(+8), cols 8*nt + 2*t4 (+1)
        float s[8][4] = {};
#pragma unroll
        for (int ks = 0; ks < 64; ks += 8) {
            const uint32_t a0 = Qs[(wm0 + g) * AST + ks + t4];
            const uint32_t a1 = Qs[(wm0 + g + 8) * AST + ks + t4];
            const uint32_t a2 = Qs[(wm0 + g) * AST + ks + 4 + t4];
            const uint32_t a3 = Qs[(wm0 + g + 8) * AST + ks + 4 + t4];
#pragma unroll
            for (int nt = 0; nt < 8; nt++) {
                const uint32_t b0 = Ks[(nt * 8 + g) * AST + ks + t4];
                const uint32_t b1 = Ks[(nt * 8 + g) * AST + ks + 4 + t4];
                mma_tf32(s[nt], a0, a1, a2, a3, b0, b1);
            }
        }

        // Causal mask (only last two tiles of each q-block need it)
        if (kt >= 2 * qt) {
#pragma unroll
            for (int nt = 0; nt < 8; nt++)
#pragma unroll
                for (int hh = 0; hh < 2; hh++)
#pragma unroll
                    for (int cc = 0; cc < 2; cc++) {
                        const int row = q0 + wm0 + g + hh * 8;
                        const int col = k0 + nt * 8 + t4 * 2 + cc;
                        if (col > row) s[nt][hh * 2 + cc] = -1e30f;
                    }
        }

        // Online softmax: each thread owns rows g and g+8 of its warp tile.
#pragma unroll
        for (int hh = 0; hh < 2; hh++) {
            float mx = -INFINITY;
#pragma unroll
            for (int nt = 0; nt < 8; nt++)
                mx = fmaxf(mx, fmaxf(s[nt][hh * 2], s[nt][hh * 2 + 1]));
            mx = fmaxf(mx, __shfl_xor_sync(0xffffffffu, mx, 1));
            mx = fmaxf(mx, __shfl_xor_sync(0xffffffffu, mx, 2));
            const float nm = fmaxf(mrow[hh], mx);
            const float corr = __expf(mrow[hh] - nm);
            float ps = 0.f;
#pragma unroll
            for (int nt = 0; nt < 8; nt++) {
                s[nt][hh * 2]     = __expf(s[nt][hh * 2] - nm);
                s[nt][hh * 2 + 1] = __expf(s[nt][hh * 2 + 1] - nm);
                ps += s[nt][hh * 2] + s[nt][hh * 2 + 1];
            }
            ps += __shfl_xor_sync(0xffffffffu, ps, 1);
            ps += __shfl_xor_sync(0xffffffffu, ps, 2);
            lrow[hh] = lrow[hh] * corr + ps;
#pragma unroll
            for (int nt = 0; nt < 8; nt++) {
                acc[nt][hh * 2]     *= corr;
                acc[nt][hh * 2 + 1] *= corr;
            }
            mrow[hh] = nm;
        }

        // P -> smem (warp-private rows, tf32)
#pragma unroll
        for (int nt = 0; nt < 8; nt++) {
            Ps[(wm0 + g) * AST + nt * 8 + t4 * 2]         = f2tf32(s[nt][0]);
            Ps[(wm0 + g) * AST + nt * 8 + t4 * 2 + 1]     = f2tf32(s[nt][1]);
            Ps[(wm0 + g + 8) * AST + nt * 8 + t4 * 2]     = f2tf32(s[nt][2]);
            Ps[(wm0 + g + 8) * AST + nt * 8 + t4 * 2 + 1] = f2tf32(s[nt][3]);
        }
        __syncwarp();

        // O += P V : contraction over j (64), output cols d = 8*nt + 2*t4
#pragma unroll
        for (int ks = 0; ks < 64; ks += 8) {
            const uint32_t a0 = Ps[(wm0 + g) * AST + ks + t4];
            const uint32_t a1 = Ps[(wm0 + g + 8) * AST + ks + t4];
            const uint32_t a2 = Ps[(wm0 + g) * AST + ks + 4 + t4];
            const uint32_t a3 = Ps[(wm0 + g + 8) * AST + ks + 4 + t4];
#pragma unroll
            for (int nt = 0; nt < 8; nt++) {
                const uint32_t b0 = Vs[(ks + t4) * AST + nt * 8 + g];
                const uint32_t b1 = Vs[(ks + 4 + t4) * AST + nt * 8 + g];
                mma_tf32(acc[nt], a0, a1, a2, a3, b0, b1);
            }
        }
    }

    // Epilogue: normalize, write [B*N, D]
    const int b_ = bh >> 4;
    const int h_ = bh & 15;
    const float inv0 = 1.f / lrow[0];
    const float inv1 = 1.f / lrow[1];
#pragma unroll
    for (int hh = 0; hh < 2; hh++) {
        const int n_ = q0 + wm0 + g + hh * 8;
        const float inv = hh ? inv1 : inv0;
        float* orow = &o[((size_t)(b_ * NTOK + n_)) * DMODEL + h_ * HDIM];
#pragma unroll
        for (int nt = 0; nt < 8; nt++) {
            float2 ov;
            ov.x = acc[nt][hh * 2] * inv;
            ov.y = acc[nt][hh * 2 + 1] * inv;
            *(float2*)&orow[nt * 8 + t4 * 2] = ov;
        }
    }
}

// ---------------------------------------------------------------------------
extern "C" void kernel_launch(void* const* d_in, const int* in_sizes, int n_in,
                              void* d_out, int out_size)
{
    const float* x  = (const float*)d_in[0];
    const float* Wq = (const float*)d_in[1];
    const float* bq = (const float*)d_in[2];
    const float* Wk = (const float*)d_in[3];
    const float* bk = (const float*)d_in[4];
    const float* Wv = (const float*)d_in[5];
    const float* bv = (const float*)d_in[6];
    const float* Wo = (const float*)d_in[7];
    const float* bo = (const float*)d_in[8];
    float* out = (float*)d_out;

    float *gq, *gk, *gv, *ga;
    cudaGetSymbolAddress((void**)&gq, g_q);
    cudaGetSymbolAddress((void**)&gk, g_k);
    cudaGetSymbolAddress((void**)&gv, g_v);
    cudaGetSymbolAddress((void**)&ga, g_attn);

    dim3 ggemm(DMODEL / 128, MROWS / 128);   // (8, 64)

    const float qscale = 0.125f;  // 1/sqrt(64)
    gemm_tf32_kernel<<<ggemm, 256>>>(x, Wq, bq, gq, 1, qscale);
    gemm_tf32_kernel<<<ggemm, 256>>>(x, Wk, bk, gk, 1, 1.f);
    gemm_tf32_kernel<<<ggemm, 256>>>(x, Wv, bv, gv, 1, 1.f);

    const int attn_smem = ATTN_SMEM_WORDS * sizeof(uint32_t);  // ~104 KB
    cudaFuncSetAttribute(attn_tc_kernel,
                         cudaFuncAttributeMaxDynamicSharedMemorySize, attn_smem);
    dim3 gattn(NTOK / 128, BATCH * NHEAD);   // (16, 64)
    attn_tc_kernel<<<gattn, 256, attn_smem>>>(gq, gk, gv, ga);

    gemm_tf32_kernel<<<ggemm, 256>>>(ga, Wo, bo, out, 0, 1.f);
}

// round 4
// speedup vs baseline: 3.1870x; 1.1116x over previous
#include <cuda_runtime.h>
#include <math.h>
#include <stdint.h>

#define BATCH 4
#define NTOK 2048
#define DMODEL 1024
#define NHEAD 16
#define HDIM 64
#define MROWS (BATCH * NTOK)   // 8192

__device__ float g_q[BATCH * NHEAD * NTOK * HDIM];     // [B,H,N,hd]
__device__ float g_k[BATCH * NHEAD * NTOK * HDIM];
__device__ float g_v[BATCH * NHEAD * NTOK * HDIM];
__device__ float g_attn[MROWS * DMODEL];               // [B*N, D]

__device__ __forceinline__ uint32_t f2tf32(float f) {
    uint32_t u;
    asm("cvt.rna.tf32.f32 %0, %1;" : "=r"(u) : "f"(f));
    return u;
}

__device__ __forceinline__ void mma_tf32(float c[4],
                                         uint32_t a0, uint32_t a1, uint32_t a2, uint32_t a3,
                                         uint32_t b0, uint32_t b1) {
    asm volatile(
        "mma.sync.aligned.m16n8k8.row.col.f32.tf32.tf32.f32 "
        "{%0,%1,%2,%3}, {%4,%5,%6,%7}, {%8,%9}, {%0,%1,%2,%3};\n"
        : "+f"(c[0]), "+f"(c[1]), "+f"(c[2]), "+f"(c[3])
        : "r"(a0), "r"(a1), "r"(a2), "r"(a3), "r"(b0), "r"(b1));
}

// ---------------------------------------------------------------------------
// TF32 tensor-core GEMM with register-prefetch pipeline.
// C = (A[8192,1024] @ W[1024,1024] + bias) * scale
// 128x128 CTA tile, BK=16, 256 threads, warp tile 64x32, m16n8k8.tf32.
// ---------------------------------------------------------------------------
#define AS_STRIDE 17
#define BS_STRIDE 132

__global__ __launch_bounds__(256, 2)
void gemm_tf32_kernel(const float* __restrict__ A,
                      const float* __restrict__ W,
                      const float* __restrict__ bias,
                      float* __restrict__ C,
                      int head_layout, float scale)
{
    __shared__ uint32_t As[128 * AS_STRIDE];
    __shared__ uint32_t Bs[16 * BS_STRIDE];

    const int t     = threadIdx.x;
    const int warp  = t >> 5;
    const int lane  = t & 31;
    const int g     = lane >> 2;
    const int tid4  = lane & 3;
    const int wm0   = (warp >> 2) * 64;
    const int wn0   = (warp & 3) * 32;

    const int m0 = blockIdx.y * 128;
    const int n0 = blockIdx.x * 128;

    const int ar0 = t >> 2;
    const int ac4 = t & 3;
    const int br0 = t >> 5;
    const int bc4 = t & 31;

    const float* pa0 = A + (size_t)(m0 + ar0) * 1024 + ac4 * 4;
    const float* pa1 = pa0 + (size_t)64 * 1024;
    const float* pb0 = W + (size_t)br0 * 1024 + n0 + bc4 * 4;
    const float* pb1 = pb0 + (size_t)8 * 1024;

    // prefetch slab 0
    float4 av0 = *(const float4*)pa0;
    float4 av1 = *(const float4*)pa1;
    float4 bv0 = *(const float4*)pb0;
    float4 bv1 = *(const float4*)pb1;

    float acc[4][4][4] = {};

    for (int k0 = 0; k0 < 1024; k0 += 16) {
        __syncthreads();
        {
            uint32_t* p = &As[ar0 * AS_STRIDE + ac4 * 4];
            p[0] = f2tf32(av0.x); p[1] = f2tf32(av0.y);
            p[2] = f2tf32(av0.z); p[3] = f2tf32(av0.w);
            uint32_t* p2 = &As[(ar0 + 64) * AS_STRIDE + ac4 * 4];
            p2[0] = f2tf32(av1.x); p2[1] = f2tf32(av1.y);
            p2[2] = f2tf32(av1.z); p2[3] = f2tf32(av1.w);
            uint32_t* qq = &Bs[br0 * BS_STRIDE + bc4 * 4];
            qq[0] = f2tf32(bv0.x); qq[1] = f2tf32(bv0.y);
            qq[2] = f2tf32(bv0.z); qq[3] = f2tf32(bv0.w);
            uint32_t* q2 = &Bs[(br0 + 8) * BS_STRIDE + bc4 * 4];
            q2[0] = f2tf32(bv1.x); q2[1] = f2tf32(bv1.y);
            q2[2] = f2tf32(bv1.z); q2[3] = f2tf32(bv1.w);
        }
        __syncthreads();

        // prefetch next slab during compute
        if (k0 + 16 < 1024) {
            av0 = *(const float4*)(pa0 + k0 + 16);
            av1 = *(const float4*)(pa1 + k0 + 16);
            bv0 = *(const float4*)(pb0 + (size_t)(k0 + 16) * 1024);
            bv1 = *(const float4*)(pb1 + (size_t)(k0 + 16) * 1024);
        }

#pragma unroll
        for (int ks = 0; ks < 16; ks += 8) {
            uint32_t afr[4][4];
            uint32_t bfr[4][2];
#pragma unroll
            for (int mi = 0; mi < 4; mi++) {
                const int r0 = wm0 + mi * 16 + g;
                afr[mi][0] = As[r0 * AS_STRIDE + ks + tid4];
                afr[mi][1] = As[(r0 + 8) * AS_STRIDE + ks + tid4];
                afr[mi][2] = As[r0 * AS_STRIDE + ks + 4 + tid4];
                afr[mi][3] = As[(r0 + 8) * AS_STRIDE + ks + 4 + tid4];
            }
#pragma unroll
            for (int ni = 0; ni < 4; ni++) {
                const int c = wn0 + ni * 8 + g;
                bfr[ni][0] = Bs[(ks + tid4) * BS_STRIDE + c];
                bfr[ni][1] = Bs[(ks + 4 + tid4) * BS_STRIDE + c];
            }
#pragma unroll
            for (int mi = 0; mi < 4; mi++)
#pragma unroll
                for (int ni = 0; ni < 4; ni++)
                    mma_tf32(acc[mi][ni], afr[mi][0], afr[mi][1], afr[mi][2], afr[mi][3],
                             bfr[ni][0], bfr[ni][1]);
        }
    }

#pragma unroll
    for (int ni = 0; ni < 4; ni++) {
        const int c = n0 + wn0 + ni * 8 + tid4 * 2;
        const float b0 = bias[c], b1 = bias[c + 1];
#pragma unroll
        for (int mi = 0; mi < 4; mi++) {
#pragma unroll
            for (int half = 0; half < 2; half++) {
                const int m = m0 + wm0 + mi * 16 + g + half * 8;
                float2 o;
                o.x = (acc[mi][ni][half * 2 + 0] + b0) * scale;
                o.y = (acc[mi][ni][half * 2 + 1] + b1) * scale;
                if (head_layout) {
                    const int b_  = m >> 11;
                    const int n_  = m & 2047;
                    const int h_  = c >> 6;
                    const int hd_ = c & 63;
                    *(float2*)&C[(((size_t)(b_ * NHEAD + h_) * NTOK) + n_) * HDIM + hd_] = o;
                } else {
                    *(float2*)&C[(size_t)m * 1024 + c] = o;
                }
            }
        }
    }
}

// ---------------------------------------------------------------------------
// Tensor-core flash attention (causal, tf32).
// BM=128 queries per CTA, BN=64 keys per iteration, 8 warps (warp = 16 rows).
// smem: Qs [128][68] | Ks [64][68] | Vs [64][72] | Ps [128][68]
// Vs stride 72 makes the transposed PV b-fragment reads conflict-free.
// ---------------------------------------------------------------------------
#define AST 68
#define VST 72
#define SM_Q 0
#define SM_K (128 * AST)
#define SM_V (SM_K + 64 * AST)
#define SM_P (SM_V + 64 * VST)
#define ATTN_SMEM_WORDS (SM_P + 128 * AST)

__global__ __launch_bounds__(256, 2)
void attn_tc_kernel(const float* __restrict__ q,
                    const float* __restrict__ k,
                    const float* __restrict__ v,
                    float* __restrict__ o)
{
    extern __shared__ uint32_t sm[];
    uint32_t* Qs = sm + SM_Q;
    uint32_t* Ks = sm + SM_K;
    uint32_t* Vs = sm + SM_V;
    uint32_t* Ps = sm + SM_P;

    const int t    = threadIdx.x;
    const int warp = t >> 5;
    const int lane = t & 31;
    const int g    = lane >> 2;
    const int t4   = lane & 3;
    const int wm0  = warp * 16;

    const int qt = blockIdx.x;
    const int bh = blockIdx.y;
    const int q0 = qt * 128;

    const float* qp = q + (size_t)bh * NTOK * HDIM;
    const float* kp = k + (size_t)bh * NTOK * HDIM;
    const float* vp = v + (size_t)bh * NTOK * HDIM;

#pragma unroll
    for (int i = 0; i < 8; i++) {
        const int idx = t + i * 256;
        const int row = idx >> 4;
        const int c4  = idx & 15;
        float4 qv = *(const float4*)&qp[(size_t)(q0 + row) * HDIM + c4 * 4];
        uint32_t* p = &Qs[row * AST + c4 * 4];
        p[0] = f2tf32(qv.x); p[1] = f2tf32(qv.y);
        p[2] = f2tf32(qv.z); p[3] = f2tf32(qv.w);
    }

    float acc[8][4] = {};
    float mrow[2] = {-INFINITY, -INFINITY};
    float lrow[2] = {0.f, 0.f};

    const int ktmax = 2 * qt + 1;
    for (int kt = 0; kt <= ktmax; kt++) {
        const int k0 = kt * 64;
        __syncthreads();
#pragma unroll
        for (int i = 0; i < 4; i++) {
            const int idx = t + i * 256;
            const int row = idx >> 4;
            const int c4  = idx & 15;
            float4 kv = *(const float4*)&kp[(size_t)(k0 + row) * HDIM + c4 * 4];
            uint32_t* pk = &Ks[row * AST + c4 * 4];
            pk[0] = f2tf32(kv.x); pk[1] = f2tf32(kv.y);
            pk[2] = f2tf32(kv.z); pk[3] = f2tf32(kv.w);
            float4 vv = *(const float4*)&vp[(size_t)(k0 + row) * HDIM + c4 * 4];
            uint32_t* pv = &Vs[row * VST + c4 * 4];
            pv[0] = f2tf32(vv.x); pv[1] = f2tf32(vv.y);
            pv[2] = f2tf32(vv.z); pv[3] = f2tf32(vv.w);
        }
        __syncthreads();

        // S = Q K^T
        float s[8][4] = {};
#pragma unroll
        for (int ks = 0; ks < 64; ks += 8) {
            const uint32_t a0 = Qs[(wm0 + g) * AST + ks + t4];
            const uint32_t a1 = Qs[(wm0 + g + 8) * AST + ks + t4];
            const uint32_t a2 = Qs[(wm0 + g) * AST + ks + 4 + t4];
            const uint32_t a3 = Qs[(wm0 + g + 8) * AST + ks + 4 + t4];
#pragma unroll
            for (int nt = 0; nt < 8; nt++) {
                const uint32_t b0 = Ks[(nt * 8 + g) * AST + ks + t4];
                const uint32_t b1 = Ks[(nt * 8 + g) * AST + ks + 4 + t4];
                mma_tf32(s[nt], a0, a1, a2, a3, b0, b1);
            }
        }

        if (kt >= 2 * qt) {
#pragma unroll
            for (int nt = 0; nt < 8; nt++)
#pragma unroll
                for (int hh = 0; hh < 2; hh++)
#pragma unroll
                    for (int cc = 0; cc < 2; cc++) {
                        const int row = q0 + wm0 + g + hh * 8;
                        const int col = k0 + nt * 8 + t4 * 2 + cc;
                        if (col > row) s[nt][hh * 2 + cc] = -1e30f;
                    }
        }

#pragma unroll
        for (int hh = 0; hh < 2; hh++) {
            float mx = -INFINITY;
#pragma unroll
            for (int nt = 0; nt < 8; nt++)
                mx = fmaxf(mx, fmaxf(s[nt][hh * 2], s[nt][hh * 2 + 1]));
            mx = fmaxf(mx, __shfl_xor_sync(0xffffffffu, mx, 1));
            mx = fmaxf(mx, __shfl_xor_sync(0xffffffffu, mx, 2));
            const float nm = fmaxf(mrow[hh], mx);
            const float corr = __expf(mrow[hh] - nm);
            float ps = 0.f;
#pragma unroll
            for (int nt = 0; nt < 8; nt++) {
                s[nt][hh * 2]     = __expf(s[nt][hh * 2] - nm);
                s[nt][hh * 2 + 1] = __expf(s[nt][hh * 2 + 1] - nm);
                ps += s[nt][hh * 2] + s[nt][hh * 2 + 1];
            }
            ps += __shfl_xor_sync(0xffffffffu, ps, 1);
            ps += __shfl_xor_sync(0xffffffffu, ps, 2);
            lrow[hh] = lrow[hh] * corr + ps;
#pragma unroll
            for (int nt = 0; nt < 8; nt++) {
                acc[nt][hh * 2]     *= corr;
                acc[nt][hh * 2 + 1] *= corr;
            }
            mrow[hh] = nm;
        }

        // P -> smem (warp-private rows)
#pragma unroll
        for (int nt = 0; nt < 8; nt++) {
            Ps[(wm0 + g) * AST + nt * 8 + t4 * 2]         = f2tf32(s[nt][0]);
            Ps[(wm0 + g) * AST + nt * 8 + t4 * 2 + 1]     = f2tf32(s[nt][1]);
            Ps[(wm0 + g + 8) * AST + nt * 8 + t4 * 2]     = f2tf32(s[nt][2]);
            Ps[(wm0 + g + 8) * AST + nt * 8 + t4 * 2 + 1] = f2tf32(s[nt][3]);
        }
        __syncwarp();

        // O += P V
#pragma unroll
        for (int ks = 0; ks < 64; ks += 8) {
            const uint32_t a0 = Ps[(wm0 + g) * AST + ks + t4];
            const uint32_t a1 = Ps[(wm0 + g + 8) * AST + ks + t4];
            const uint32_t a2 = Ps[(wm0 + g) * AST + ks + 4 + t4];
            const uint32_t a3 = Ps[(wm0 + g + 8) * AST + ks + 4 + t4];
#pragma unroll
            for (int nt = 0; nt < 8; nt++) {
                const uint32_t b0 = Vs[(ks + t4) * VST + nt * 8 + g];
                const uint32_t b1 = Vs[(ks + 4 + t4) * VST + nt * 8 + g];
                mma_tf32(acc[nt], a0, a1, a2, a3, b0, b1);
            }
        }
    }

    const int b_ = bh >> 4;
    const int h_ = bh & 15;
    const float inv0 = 1.f / lrow[0];
    const float inv1 = 1.f / lrow[1];
#pragma unroll
    for (int hh = 0; hh < 2; hh++) {
        const int n_ = q0 + wm0 + g + hh * 8;
        const float inv = hh ? inv1 : inv0;
        float* orow = &o[((size_t)(b_ * NTOK + n_)) * DMODEL + h_ * HDIM];
#pragma unroll
        for (int nt = 0; nt < 8; nt++) {
            float2 ov;
            ov.x = acc[nt][hh * 2] * inv;
            ov.y = acc[nt][hh * 2 + 1] * inv;
            *(float2*)&orow[nt * 8 + t4 * 2] = ov;
        }
    }
}

// ---------------------------------------------------------------------------
extern "C" void kernel_launch(void* const* d_in, const int* in_sizes, int n_in,
                              void* d_out, int out_size)
{
    const float* x  = (const float*)d_in[0];
    const float* Wq = (const float*)d_in[1];
    const float* bq = (const float*)d_in[2];
    const float* Wk = (const float*)d_in[3];
    const float* bk = (const float*)d_in[4];
    const float* Wv = (const float*)d_in[5];
    const float* bv = (const float*)d_in[6];
    const float* Wo = (const float*)d_in[7];
    const float* bo = (const float*)d_in[8];
    float* out = (float*)d_out;

    float *gq, *gk, *gv, *ga;
    cudaGetSymbolAddress((void**)&gq, g_q);
    cudaGetSymbolAddress((void**)&gk, g_k);
    cudaGetSymbolAddress((void**)&gv, g_v);
    cudaGetSymbolAddress((void**)&ga, g_attn);

    dim3 ggemm(DMODEL / 128, MROWS / 128);   // (8, 64)

    const float qscale = 0.125f;  // 1/sqrt(64)
    gemm_tf32_kernel<<<ggemm, 256>>>(x, Wq, bq, gq, 1, qscale);
    gemm_tf32_kernel<<<ggemm, 256>>>(x, Wk, bk, gk, 1, 1.f);
    gemm_tf32_kernel<<<ggemm, 256>>>(x, Wv, bv, gv, 1, 1.f);

    const int attn_smem = ATTN_SMEM_WORDS * sizeof(uint32_t);  // ~105.5 KB
    cudaFuncSetAttribute(attn_tc_kernel,
                         cudaFuncAttributeMaxDynamicSharedMemorySize, attn_smem);
    dim3 gattn(NTOK / 128, BATCH * NHEAD);   // (16, 64)
    attn_tc_kernel<<<gattn, 256, attn_smem>>>(gq, gk, gv, ga);

    gemm_tf32_kernel<<<ggemm, 256>>>(ga, Wo, bo, out, 0, 1.f);
}

// round 5
// speedup vs baseline: 3.3828x; 1.0614x over previous
#include <cuda_runtime.h>
#include <math.h>
#include <stdint.h>

#define BATCH 4
#define NTOK 2048
#define DMODEL 1024
#define NHEAD 16
#define HDIM 64
#define MROWS (BATCH * NTOK)   // 8192

__device__ float g_q[BATCH * NHEAD * NTOK * HDIM];     // [B,H,N,hd]
__device__ float g_k[BATCH * NHEAD * NTOK * HDIM];
__device__ float g_v[BATCH * NHEAD * NTOK * HDIM];
__device__ float g_attn[MROWS * DMODEL];               // [B*N, D]

__device__ __forceinline__ uint32_t f2tf32(float f) {
    uint32_t u;
    asm("cvt.rna.tf32.f32 %0, %1;" : "=r"(u) : "f"(f));
    return u;
}

__device__ __forceinline__ void mma_tf32(float c[4],
                                         uint32_t a0, uint32_t a1, uint32_t a2, uint32_t a3,
                                         uint32_t b0, uint32_t b1) {
    asm volatile(
        "mma.sync.aligned.m16n8k8.row.col.f32.tf32.tf32.f32 "
        "{%0,%1,%2,%3}, {%4,%5,%6,%7}, {%8,%9}, {%0,%1,%2,%3};\n"
        : "+f"(c[0]), "+f"(c[1]), "+f"(c[2]), "+f"(c[3])
        : "r"(a0), "r"(a1), "r"(a2), "r"(a3), "r"(b0), "r"(b1));
}

// ---------------------------------------------------------------------------
// TF32 tensor-core GEMM, double-buffered smem (1 sync per K-slab).
// qkv_mode: blockIdx.z selects (W,bias,out,scale) among q/k/v; if W1==nullptr
// only z=0 is used (output projection).
// ---------------------------------------------------------------------------
#define AS_STRIDE 17
#define BS_STRIDE 132
#define AS_WORDS (128 * AS_STRIDE)   // 2176
#define BS_WORDS (16 * BS_STRIDE)    // 2112

__global__ __launch_bounds__(256, 2)
void gemm_tf32_kernel(const float* __restrict__ A,
                      const float* __restrict__ W0,
                      const float* __restrict__ b0p,
                      float* __restrict__ C0,
                      const float* __restrict__ W1,
                      const float* __restrict__ b1p,
                      float* __restrict__ C1,
                      const float* __restrict__ W2,
                      const float* __restrict__ b2p,
                      float* __restrict__ C2,
                      int head_layout, float scale0)
{
    __shared__ uint32_t As[2 * AS_WORDS];
    __shared__ uint32_t Bs[2 * BS_WORDS];

    const int z = blockIdx.z;
    const float* W    = (z == 0) ? W0 : (z == 1) ? W1 : W2;
    const float* bias = (z == 0) ? b0p : (z == 1) ? b1p : b2p;
    float* C          = (z == 0) ? C0 : (z == 1) ? C1 : C2;
    const float scale = (z == 0) ? scale0 : 1.f;

    const int t     = threadIdx.x;
    const int warp  = t >> 5;
    const int lane  = t & 31;
    const int g     = lane >> 2;
    const int tid4  = lane & 3;
    const int wm0   = (warp >> 2) * 64;
    const int wn0   = (warp & 3) * 32;

    const int m0 = blockIdx.y * 128;
    const int n0 = blockIdx.x * 128;

    const int ar0 = t >> 2;
    const int ac4 = t & 3;
    const int br0 = t >> 5;
    const int bc4 = t & 31;

    const float* pa0 = A + (size_t)(m0 + ar0) * 1024 + ac4 * 4;
    const float* pa1 = pa0 + (size_t)64 * 1024;
    const float* pb0 = W + (size_t)br0 * 1024 + n0 + bc4 * 4;
    const float* pb1 = pb0 + (size_t)8 * 1024;

    // slab 0 -> registers -> buffer 0
    float4 av0 = *(const float4*)pa0;
    float4 av1 = *(const float4*)pa1;
    float4 bv0 = *(const float4*)pb0;
    float4 bv1 = *(const float4*)pb1;
    {
        uint32_t* p = &As[ar0 * AS_STRIDE + ac4 * 4];
        p[0] = f2tf32(av0.x); p[1] = f2tf32(av0.y);
        p[2] = f2tf32(av0.z); p[3] = f2tf32(av0.w);
        uint32_t* p2 = &As[(ar0 + 64) * AS_STRIDE + ac4 * 4];
        p2[0] = f2tf32(av1.x); p2[1] = f2tf32(av1.y);
        p2[2] = f2tf32(av1.z); p2[3] = f2tf32(av1.w);
        uint32_t* qq = &Bs[br0 * BS_STRIDE + bc4 * 4];
        qq[0] = f2tf32(bv0.x); qq[1] = f2tf32(bv0.y);
        qq[2] = f2tf32(bv0.z); qq[3] = f2tf32(bv0.w);
        uint32_t* q2 = &Bs[(br0 + 8) * BS_STRIDE + bc4 * 4];
        q2[0] = f2tf32(bv1.x); q2[1] = f2tf32(bv1.y);
        q2[2] = f2tf32(bv1.z); q2[3] = f2tf32(bv1.w);
    }
    __syncthreads();

    float acc[4][4][4] = {};
    int cur = 0;

    for (int k0 = 0; k0 < 1024; k0 += 16) {
        const bool has_next = (k0 + 16 < 1024);
        if (has_next) {
            av0 = *(const float4*)(pa0 + k0 + 16);
            av1 = *(const float4*)(pa1 + k0 + 16);
            bv0 = *(const float4*)(pb0 + (size_t)(k0 + 16) * 1024);
            bv1 = *(const float4*)(pb1 + (size_t)(k0 + 16) * 1024);
        }

        const uint32_t* Ac = &As[cur * AS_WORDS];
        const uint32_t* Bc = &Bs[cur * BS_WORDS];
#pragma unroll
        for (int ks = 0; ks < 16; ks += 8) {
            uint32_t afr[4][4];
            uint32_t bfr[4][2];
#pragma unroll
            for (int mi = 0; mi < 4; mi++) {
                const int r0 = wm0 + mi * 16 + g;
                afr[mi][0] = Ac[r0 * AS_STRIDE + ks + tid4];
                afr[mi][1] = Ac[(r0 + 8) * AS_STRIDE + ks + tid4];
                afr[mi][2] = Ac[r0 * AS_STRIDE + ks + 4 + tid4];
                afr[mi][3] = Ac[(r0 + 8) * AS_STRIDE + ks + 4 + tid4];
            }
#pragma unroll
            for (int ni = 0; ni < 4; ni++) {
                const int c = wn0 + ni * 8 + g;
                bfr[ni][0] = Bc[(ks + tid4) * BS_STRIDE + c];
                bfr[ni][1] = Bc[(ks + 4 + tid4) * BS_STRIDE + c];
            }
#pragma unroll
            for (int mi = 0; mi < 4; mi++)
#pragma unroll
                for (int ni = 0; ni < 4; ni++)
                    mma_tf32(acc[mi][ni], afr[mi][0], afr[mi][1], afr[mi][2], afr[mi][3],
                             bfr[ni][0], bfr[ni][1]);
        }

        if (has_next) {
            uint32_t* An = &As[(cur ^ 1) * AS_WORDS];
            uint32_t* Bn = &Bs[(cur ^ 1) * BS_WORDS];
            uint32_t* p = &An[ar0 * AS_STRIDE + ac4 * 4];
            p[0] = f2tf32(av0.x); p[1] = f2tf32(av0.y);
            p[2] = f2tf32(av0.z); p[3] = f2tf32(av0.w);
            uint32_t* p2 = &An[(ar0 + 64) * AS_STRIDE + ac4 * 4];
            p2[0] = f2tf32(av1.x); p2[1] = f2tf32(av1.y);
            p2[2] = f2tf32(av1.z); p2[3] = f2tf32(av1.w);
            uint32_t* qq = &Bn[br0 * BS_STRIDE + bc4 * 4];
            qq[0] = f2tf32(bv0.x); qq[1] = f2tf32(bv0.y);
            qq[2] = f2tf32(bv0.z); qq[3] = f2tf32(bv0.w);
            uint32_t* q2 = &Bn[(br0 + 8) * BS_STRIDE + bc4 * 4];
            q2[0] = f2tf32(bv1.x); q2[1] = f2tf32(bv1.y);
            q2[2] = f2tf32(bv1.z); q2[3] = f2tf32(bv1.w);
            __syncthreads();
        }
        cur ^= 1;
    }

#pragma unroll
    for (int ni = 0; ni < 4; ni++) {
        const int c = n0 + wn0 + ni * 8 + tid4 * 2;
        const float b0 = bias[c], b1 = bias[c + 1];
#pragma unroll
        for (int mi = 0; mi < 4; mi++) {
#pragma unroll
            for (int half = 0; half < 2; half++) {
                const int m = m0 + wm0 + mi * 16 + g + half * 8;
                float2 o;
                o.x = (acc[mi][ni][half * 2 + 0] + b0) * scale;
                o.y = (acc[mi][ni][half * 2 + 1] + b1) * scale;
                if (head_layout) {
                    const int b_  = m >> 11;
                    const int n_  = m & 2047;
                    const int h_  = c >> 6;
                    const int hd_ = c & 63;
                    *(float2*)&C[(((size_t)(b_ * NHEAD + h_) * NTOK) + n_) * HDIM + hd_] = o;
                } else {
                    *(float2*)&C[(size_t)m * 1024 + c] = o;
                }
            }
        }
    }
}

// ---------------------------------------------------------------------------
// Tensor-core flash attention (causal, tf32) — unchanged from R3.
// ---------------------------------------------------------------------------
#define AST 68
#define VST 72
#define SM_Q 0
#define SM_K (128 * AST)
#define SM_V (SM_K + 64 * AST)
#define SM_P (SM_V + 64 * VST)
#define ATTN_SMEM_WORDS (SM_P + 128 * AST)

__global__ __launch_bounds__(256, 2)
void attn_tc_kernel(const float* __restrict__ q,
                    const float* __restrict__ k,
                    const float* __restrict__ v,
                    float* __restrict__ o)
{
    extern __shared__ uint32_t sm[];
    uint32_t* Qs = sm + SM_Q;
    uint32_t* Ks = sm + SM_K;
    uint32_t* Vs = sm + SM_V;
    uint32_t* Ps = sm + SM_P;

    const int t    = threadIdx.x;
    const int warp = t >> 5;
    const int lane = t & 31;
    const int g    = lane >> 2;
    const int t4   = lane & 3;
    const int wm0  = warp * 16;

    const int qt = blockIdx.x;
    const int bh = blockIdx.y;
    const int q0 = qt * 128;

    const float* qp = q + (size_t)bh * NTOK * HDIM;
    const float* kp = k + (size_t)bh * NTOK * HDIM;
    const float* vp = v + (size_t)bh * NTOK * HDIM;

#pragma unroll
    for (int i = 0; i < 8; i++) {
        const int idx = t + i * 256;
        const int row = idx >> 4;
        const int c4  = idx & 15;
        float4 qv = *(const float4*)&qp[(size_t)(q0 + row) * HDIM + c4 * 4];
        uint32_t* p = &Qs[row * AST + c4 * 4];
        p[0] = f2tf32(qv.x); p[1] = f2tf32(qv.y);
        p[2] = f2tf32(qv.z); p[3] = f2tf32(qv.w);
    }

    float acc[8][4] = {};
    float mrow[2] = {-INFINITY, -INFINITY};
    float lrow[2] = {0.f, 0.f};

    const int ktmax = 2 * qt + 1;
    for (int kt = 0; kt <= ktmax; kt++) {
        const int k0 = kt * 64;
        __syncthreads();
#pragma unroll
        for (int i = 0; i < 4; i++) {
            const int idx = t + i * 256;
            const int row = idx >> 4;
            const int c4  = idx & 15;
            float4 kv = *(const float4*)&kp[(size_t)(k0 + row) * HDIM + c4 * 4];
            uint32_t* pk = &Ks[row * AST + c4 * 4];
            pk[0] = f2tf32(kv.x); pk[1] = f2tf32(kv.y);
            pk[2] = f2tf32(kv.z); pk[3] = f2tf32(kv.w);
            float4 vv = *(const float4*)&vp[(size_t)(k0 + row) * HDIM + c4 * 4];
            uint32_t* pv = &Vs[row * VST + c4 * 4];
            pv[0] = f2tf32(vv.x); pv[1] = f2tf32(vv.y);
            pv[2] = f2tf32(vv.z); pv[3] = f2tf32(vv.w);
        }
        __syncthreads();

        float s[8][4] = {};
#pragma unroll
        for (int ks = 0; ks < 64; ks += 8) {
            const uint32_t a0 = Qs[(wm0 + g) * AST + ks + t4];
            const uint32_t a1 = Qs[(wm0 + g + 8) * AST + ks + t4];
            const uint32_t a2 = Qs[(wm0 + g) * AST + ks + 4 + t4];
            const uint32_t a3 = Qs[(wm0 + g + 8) * AST + ks + 4 + t4];
#pragma unroll
            for (int nt = 0; nt < 8; nt++) {
                const uint32_t b0 = Ks[(nt * 8 + g) * AST + ks + t4];
                const uint32_t b1 = Ks[(nt * 8 + g) * AST + ks + 4 + t4];
                mma_tf32(s[nt], a0, a1, a2, a3, b0, b1);
            }
        }

        if (kt >= 2 * qt) {
#pragma unroll
            for (int nt = 0; nt < 8; nt++)
#pragma unroll
                for (int hh = 0; hh < 2; hh++)
#pragma unroll
                    for (int cc = 0; cc < 2; cc++) {
                        const int row = q0 + wm0 + g + hh * 8;
                        const int col = k0 + nt * 8 + t4 * 2 + cc;
                        if (col > row) s[nt][hh * 2 + cc] = -1e30f;
                    }
        }

#pragma unroll
        for (int hh = 0; hh < 2; hh++) {
            float mx = -INFINITY;
#pragma unroll
            for (int nt = 0; nt < 8; nt++)
                mx = fmaxf(mx, fmaxf(s[nt][hh * 2], s[nt][hh * 2 + 1]));
            mx = fmaxf(mx, __shfl_xor_sync(0xffffffffu, mx, 1));
            mx = fmaxf(mx, __shfl_xor_sync(0xffffffffu, mx, 2));
            const float nm = fmaxf(mrow[hh], mx);
            const float corr = __expf(mrow[hh] - nm);
            float ps = 0.f;
#pragma unroll
            for (int nt = 0; nt < 8; nt++) {
                s[nt][hh * 2]     = __expf(s[nt][hh * 2] - nm);
                s[nt][hh * 2 + 1] = __expf(s[nt][hh * 2 + 1] - nm);
                ps += s[nt][hh * 2] + s[nt][hh * 2 + 1];
            }
            ps += __shfl_xor_sync(0xffffffffu, ps, 1);
            ps += __shfl_xor_sync(0xffffffffu, ps, 2);
            lrow[hh] = lrow[hh] * corr + ps;
#pragma unroll
            for (int nt = 0; nt < 8; nt++) {
                acc[nt][hh * 2]     *= corr;
                acc[nt][hh * 2 + 1] *= corr;
            }
            mrow[hh] = nm;
        }

#pragma unroll
        for (int nt = 0; nt < 8; nt++) {
            Ps[(wm0 + g) * AST + nt * 8 + t4 * 2]         = f2tf32(s[nt][0]);
            Ps[(wm0 + g) * AST + nt * 8 + t4 * 2 + 1]     = f2tf32(s[nt][1]);
            Ps[(wm0 + g + 8) * AST + nt * 8 + t4 * 2]     = f2tf32(s[nt][2]);
            Ps[(wm0 + g + 8) * AST + nt * 8 + t4 * 2 + 1] = f2tf32(s[nt][3]);
        }
        __syncwarp();

#pragma unroll
        for (int ks = 0; ks < 64; ks += 8) {
            const uint32_t a0 = Ps[(wm0 + g) * AST + ks + t4];
            const uint32_t a1 = Ps[(wm0 + g + 8) * AST + ks + t4];
            const uint32_t a2 = Ps[(wm0 + g) * AST + ks + 4 + t4];
            const uint32_t a3 = Ps[(wm0 + g + 8) * AST + ks + 4 + t4];
#pragma unroll
            for (int nt = 0; nt < 8; nt++) {
                const uint32_t b0 = Vs[(ks + t4) * VST + nt * 8 + g];
                const uint32_t b1 = Vs[(ks + 4 + t4) * VST + nt * 8 + g];
                mma_tf32(acc[nt], a0, a1, a2, a3, b0, b1);
            }
        }
    }

    const int b_ = bh >> 4;
    const int h_ = bh & 15;
    const float inv0 = 1.f / lrow[0];
    const float inv1 = 1.f / lrow[1];
#pragma unroll
    for (int hh = 0; hh < 2; hh++) {
        const int n_ = q0 + wm0 + g + hh * 8;
        const float inv = hh ? inv1 : inv0;
        float* orow = &o[((size_t)(b_ * NTOK + n_)) * DMODEL + h_ * HDIM];
#pragma unroll
        for (int nt = 0; nt < 8; nt++) {
            float2 ov;
            ov.x = acc[nt][hh * 2] * inv;
            ov.y = acc[nt][hh * 2 + 1] * inv;
            *(float2*)&orow[nt * 8 + t4 * 2] = ov;
        }
    }
}

// ---------------------------------------------------------------------------
extern "C" void kernel_launch(void* const* d_in, const int* in_sizes, int n_in,
                              void* d_out, int out_size)
{
    const float* x  = (const float*)d_in[0];
    const float* Wq = (const float*)d_in[1];
    const float* bq = (const float*)d_in[2];
    const float* Wk = (const float*)d_in[3];
    const float* bk = (const float*)d_in[4];
    const float* Wv = (const float*)d_in[5];
    const float* bv = (const float*)d_in[6];
    const float* Wo = (const float*)d_in[7];
    const float* bo = (const float*)d_in[8];
    float* out = (float*)d_out;

    float *gq, *gk, *gv, *ga;
    cudaGetSymbolAddress((void**)&gq, g_q);
    cudaGetSymbolAddress((void**)&gk, g_k);
    cudaGetSymbolAddress((void**)&gv, g_v);
    cudaGetSymbolAddress((void**)&ga, g_attn);

    const float qscale = 0.125f;  // 1/sqrt(64)

    // Fused QKV: one launch, blockIdx.z in {0,1,2}
    dim3 gqkv(DMODEL / 128, MROWS / 128, 3);
    gemm_tf32_kernel<<<gqkv, 256>>>(x,
                                    Wq, bq, gq,
                                    Wk, bk, gk,
                                    Wv, bv, gv,
                                    1, qscale);

    const int attn_smem = ATTN_SMEM_WORDS * sizeof(uint32_t);  // ~105.5 KB
    cudaFuncSetAttribute(attn_tc_kernel,
                         cudaFuncAttributeMaxDynamicSharedMemorySize, attn_smem);
    dim3 gattn(NTOK / 128, BATCH * NHEAD);   // (16, 64)
    attn_tc_kernel<<<gattn, 256, attn_smem>>>(gq, gk, gv, ga);

    dim3 ggemm(DMODEL / 128, MROWS / 128, 1);
    gemm_tf32_kernel<<<ggemm, 256>>>(ga,
                                     Wo, bo, out,
                                     nullptr, nullptr, nullptr,
                                     nullptr, nullptr, nullptr,
                                     0, 1.f);
}

// round 7
// speedup vs baseline: 4.1700x; 1.2327x over previous
#include <cuda_runtime.h>
#include <math.h>
#include <stdint.h>

#define BATCH 4
#define NTOK 2048
#define DMODEL 1024
#define NHEAD 16
#define HDIM 64
#define MROWS (BATCH * NTOK)   // 8192

__device__ float g_q[BATCH * NHEAD * NTOK * HDIM];     // [B,H,N,hd]
__device__ float g_k[BATCH * NHEAD * NTOK * HDIM];
__device__ float g_v[BATCH * NHEAD * NTOK * HDIM];
__device__ float g_attn[MROWS * DMODEL];               // [B*N, D]

__device__ __forceinline__ uint32_t f2tf32(float f) {
    uint32_t u;
    asm("cvt.rna.tf32.f32 %0, %1;" : "=r"(u) : "f"(f));
    return u;
}

__device__ __forceinline__ void mma_tf32(float c[4],
                                         uint32_t a0, uint32_t a1, uint32_t a2, uint32_t a3,
                                         uint32_t b0, uint32_t b1) {
    asm volatile(
        "mma.sync.aligned.m16n8k8.row.col.f32.tf32.tf32.f32 "
        "{%0,%1,%2,%3}, {%4,%5,%6,%7}, {%8,%9}, {%0,%1,%2,%3};\n"
        : "+f"(c[0]), "+f"(c[1]), "+f"(c[2]), "+f"(c[3])
        : "r"(a0), "r"(a1), "r"(a2), "r"(a3), "r"(b0), "r"(b1));
}

// ---------------------------------------------------------------------------
// TF32 tensor-core GEMM, double-buffered, conflict-free smem strides.
// CTA tile 128x128, BK=16, 128 threads = 4 warps, warp tile 64x64 (4x8 mma).
// blockIdx.z selects among up to 3 (W,bias,C) sets (fused QKV).
// ---------------------------------------------------------------------------
#define AS_STRIDE 20                 // 16 + 4 pad: (20g+t4) mod 32 all distinct
#define BS_STRIDE 136                // 128 + 8 pad: (8t4+g) mod 32 all distinct
#define AS_WORDS (128 * AS_STRIDE)   // 2560
#define BS_WORDS (16 * BS_STRIDE)    // 2176

__global__ __launch_bounds__(128, 2)
void gemm_tf32_kernel(const float* __restrict__ A,
                      const float* __restrict__ W0,
                      const float* __restrict__ b0p,
                      float* __restrict__ C0,
                      const float* __restrict__ W1,
                      const float* __restrict__ b1p,
                      float* __restrict__ C1,
                      const float* __restrict__ W2,
                      const float* __restrict__ b2p,
                      float* __restrict__ C2,
                      int head_layout, float scale0)
{
    __shared__ uint32_t As[2 * AS_WORDS];
    __shared__ uint32_t Bs[2 * BS_WORDS];

    const int z = blockIdx.z;
    const float* W    = (z == 0) ? W0 : (z == 1) ? W1 : W2;
    const float* bias = (z == 0) ? b0p : (z == 1) ? b1p : b2p;
    float* C          = (z == 0) ? C0 : (z == 1) ? C1 : C2;
    const float scale = (z == 0) ? scale0 : 1.f;

    const int t     = threadIdx.x;
    const int warp  = t >> 5;           // 0..3
    const int lane  = t & 31;
    const int g     = lane >> 2;
    const int tid4  = lane & 3;
    const int wm0   = (warp >> 1) * 64; // 0 / 64
    const int wn0   = (warp & 1) * 64;  // 0 / 64

    const int m0 = blockIdx.y * 128;
    const int n0 = blockIdx.x * 128;

    // global-load coordinates (128 threads)
    const int ar0 = t >> 2;             // A rows ar0 + {0,32,64,96}
    const int ac4 = t & 3;              // float4 col within 16-wide K slab
    const int br0 = t >> 5;             // B rows br0 + {0,4,8,12}
    const int bc4 = t & 31;             // float4 col within 128-wide N slab

    const float* pa = A + (size_t)(m0 + ar0) * 1024 + ac4 * 4;
    const float* pb = W + (size_t)br0 * 1024 + n0 + bc4 * 4;

    float4 av[4], bv[4];
#pragma unroll
    for (int r = 0; r < 4; r++) {
        av[r] = *(const float4*)(pa + (size_t)(r * 32) * 1024);
        bv[r] = *(const float4*)(pb + (size_t)(r * 4) * 1024);
    }
    // slab 0 -> buffer 0
#pragma unroll
    for (int r = 0; r < 4; r++) {
        uint32_t* p = &As[(ar0 + r * 32) * AS_STRIDE + ac4 * 4];
        p[0] = f2tf32(av[r].x); p[1] = f2tf32(av[r].y);
        p[2] = f2tf32(av[r].z); p[3] = f2tf32(av[r].w);
        uint32_t* q = &Bs[(br0 + r * 4) * BS_STRIDE + bc4 * 4];
        q[0] = f2tf32(bv[r].x); q[1] = f2tf32(bv[r].y);
        q[2] = f2tf32(bv[r].z); q[3] = f2tf32(bv[r].w);
    }
    __syncthreads();

    float acc[4][8][4] = {};
    int cur = 0;

    for (int k0 = 0; k0 < 1024; k0 += 16) {
        const bool has_next = (k0 + 16 < 1024);
        if (has_next) {
#pragma unroll
            for (int r = 0; r < 4; r++) {
                av[r] = *(const float4*)(pa + (size_t)(r * 32) * 1024 + k0 + 16);
                bv[r] = *(const float4*)(pb + (size_t)(r * 4 + k0 + 16) * 1024);
            }
        }

        const uint32_t* Ac = &As[cur * AS_WORDS];
        const uint32_t* Bc = &Bs[cur * BS_WORDS];
#pragma unroll
        for (int ks = 0; ks < 16; ks += 8) {
            uint32_t afr[4][4];
            uint32_t bfr[8][2];
#pragma unroll
            for (int mi = 0; mi < 4; mi++) {
                const int r0 = wm0 + mi * 16 + g;
                afr[mi][0] = Ac[r0 * AS_STRIDE + ks + tid4];
                afr[mi][1] = Ac[(r0 + 8) * AS_STRIDE + ks + tid4];
                afr[mi][2] = Ac[r0 * AS_STRIDE + ks + 4 + tid4];
                afr[mi][3] = Ac[(r0 + 8) * AS_STRIDE + ks + 4 + tid4];
            }
#pragma unroll
            for (int ni = 0; ni < 8; ni++) {
                const int c = wn0 + ni * 8 + g;
                bfr[ni][0] = Bc[(ks + tid4) * BS_STRIDE + c];
                bfr[ni][1] = Bc[(ks + 4 + tid4) * BS_STRIDE + c];
            }
#pragma unroll
            for (int mi = 0; mi < 4; mi++)
#pragma unroll
                for (int ni = 0; ni < 8; ni++)
                    mma_tf32(acc[mi][ni], afr[mi][0], afr[mi][1], afr[mi][2], afr[mi][3],
                             bfr[ni][0], bfr[ni][1]);
        }

        if (has_next) {
            uint32_t* An = &As[(cur ^ 1) * AS_WORDS];
            uint32_t* Bn = &Bs[(cur ^ 1) * BS_WORDS];
#pragma unroll
            for (int r = 0; r < 4; r++) {
                uint32_t* p = &An[(ar0 + r * 32) * AS_STRIDE + ac4 * 4];
                p[0] = f2tf32(av[r].x); p[1] = f2tf32(av[r].y);
                p[2] = f2tf32(av[r].z); p[3] = f2tf32(av[r].w);
                uint32_t* q = &Bn[(br0 + r * 4) * BS_STRIDE + bc4 * 4];
                q[0] = f2tf32(bv[r].x); q[1] = f2tf32(bv[r].y);
                q[2] = f2tf32(bv[r].z); q[3] = f2tf32(bv[r].w);
            }
            __syncthreads();
        }
        cur ^= 1;
    }

#pragma unroll
    for (int ni = 0; ni < 8; ni++) {
        const int c = n0 + wn0 + ni * 8 + tid4 * 2;
        const float b0 = bias[c], b1 = bias[c + 1];
#pragma unroll
        for (int mi = 0; mi < 4; mi++) {
#pragma unroll
            for (int half = 0; half < 2; half++) {
                const int m = m0 + wm0 + mi * 16 + g + half * 8;
                float2 o;
                o.x = (acc[mi][ni][half * 2 + 0] + b0) * scale;
                o.y = (acc[mi][ni][half * 2 + 1] + b1) * scale;
                if (head_layout) {
                    const int b_  = m >> 11;
                    const int n_  = m & 2047;
                    const int h_  = c >> 6;
                    const int hd_ = c & 63;
                    *(float2*)&C[(((size_t)(b_ * NHEAD + h_) * NTOK) + n_) * HDIM + hd_] = o;
                } else {
                    *(float2*)&C[(size_t)m * 1024 + c] = o;
                }
            }
        }
    }
}

// ---------------------------------------------------------------------------
// Tensor-core flash attention (causal, tf32) — unchanged from R4.
// ---------------------------------------------------------------------------
#define AST 68
#define VST 72
#define SM_Q 0
#define SM_K (128 * AST)
#define SM_V (SM_K + 64 * AST)
#define SM_P (SM_V + 64 * VST)
#define ATTN_SMEM_WORDS (SM_P + 128 * AST)

__global__ __launch_bounds__(256, 2)
void attn_tc_kernel(const float* __restrict__ q,
                    const float* __restrict__ k,
                    const float* __restrict__ v,
                    float* __restrict__ o)
{
    extern __shared__ uint32_t sm[];
    uint32_t* Qs = sm + SM_Q;
    uint32_t* Ks = sm + SM_K;
    uint32_t* Vs = sm + SM_V;
    uint32_t* Ps = sm + SM_P;

    const int t    = threadIdx.x;
    const int warp = t >> 5;
    const int lane = t & 31;
    const int g    = lane >> 2;
    const int t4   = lane & 3;
    const int wm0  = warp * 16;

    const int qt = blockIdx.x;
    const int bh = blockIdx.y;
    const int q0 = qt * 128;

    const float* qp = q + (size_t)bh * NTOK * HDIM;
    const float* kp = k + (size_t)bh * NTOK * HDIM;
    const float* vp = v + (size_t)bh * NTOK * HDIM;

#pragma unroll
    for (int i = 0; i < 8; i++) {
        const int idx = t + i * 256;
        const int row = idx >> 4;
        const int c4  = idx & 15;
        float4 qv = *(const float4*)&qp[(size_t)(q0 + row) * HDIM + c4 * 4];
        uint32_t* p = &Qs[row * AST + c4 * 4];
        p[0] = f2tf32(qv.x); p[1] = f2tf32(qv.y);
        p[2] = f2tf32(qv.z); p[3] = f2tf32(qv.w);
    }

    float acc[8][4] = {};
    float mrow[2] = {-INFINITY, -INFINITY};
    float lrow[2] = {0.f, 0.f};

    const int ktmax = 2 * qt + 1;
    for (int kt = 0; kt <= ktmax; kt++) {
        const int k0 = kt * 64;
        __syncthreads();
#pragma unroll
        for (int i = 0; i < 4; i++) {
            const int idx = t + i * 256;
            const int row = idx >> 4;
            const int c4  = idx & 15;
            float4 kv = *(const float4*)&kp[(size_t)(k0 + row) * HDIM + c4 * 4];
            uint32_t* pk = &Ks[row * AST + c4 * 4];
            pk[0] = f2tf32(kv.x); pk[1] = f2tf32(kv.y);
            pk[2] = f2tf32(kv.z); pk[3] = f2tf32(kv.w);
            float4 vv = *(const float4*)&vp[(size_t)(k0 + row) * HDIM + c4 * 4];
            uint32_t* pv = &Vs[row * VST + c4 * 4];
            pv[0] = f2tf32(vv.x); pv[1] = f2tf32(vv.y);
            pv[2] = f2tf32(vv.z); pv[3] = f2tf32(vv.w);
        }
        __syncthreads();

        float s[8][4] = {};
#pragma unroll
        for (int ks = 0; ks < 64; ks += 8) {
            const uint32_t a0 = Qs[(wm0 + g) * AST + ks + t4];
            const uint32_t a1 = Qs[(wm0 + g + 8) * AST + ks + t4];
            const uint32_t a2 = Qs[(wm0 + g) * AST + ks + 4 + t4];
            const uint32_t a3 = Qs[(wm0 + g + 8) * AST + ks + 4 + t4];
#pragma unroll
            for (int nt = 0; nt < 8; nt++) {
                const uint32_t b0 = Ks[(nt * 8 + g) * AST + ks + t4];
                const uint32_t b1 = Ks[(nt * 8 + g) * AST + ks + 4 + t4];
                mma_tf32(s[nt], a0, a1, a2, a3, b0, b1);
            }
        }

        if (kt >= 2 * qt) {
#pragma unroll
            for (int nt = 0; nt < 8; nt++)
#pragma unroll
                for (int hh = 0; hh < 2; hh++)
#pragma unroll
                    for (int cc = 0; cc < 2; cc++) {
                        const int row = q0 + wm0 + g + hh * 8;
                        const int col = k0 + nt * 8 + t4 * 2 + cc;
                        if (col > row) s[nt][hh * 2 + cc] = -1e30f;
                    }
        }

#pragma unroll
        for (int hh = 0; hh < 2; hh++) {
            float mx = -INFINITY;
#pragma unroll
            for (int nt = 0; nt < 8; nt++)
                mx = fmaxf(mx, fmaxf(s[nt][hh * 2], s[nt][hh * 2 + 1]));
            mx = fmaxf(mx, __shfl_xor_sync(0xffffffffu, mx, 1));
            mx = fmaxf(mx, __shfl_xor_sync(0xffffffffu, mx, 2));
            const float nm = fmaxf(mrow[hh], mx);
            const float corr = __expf(mrow[hh] - nm);
            float ps = 0.f;
#pragma unroll
            for (int nt = 0; nt < 8; nt++) {
                s[nt][hh * 2]     = __expf(s[nt][hh * 2] - nm);
                s[nt][hh * 2 + 1] = __expf(s[nt][hh * 2 + 1] - nm);
                ps += s[nt][hh * 2] + s[nt][hh * 2 + 1];
            }
            ps += __shfl_xor_sync(0xffffffffu, ps, 1);
            ps += __shfl_xor_sync(0xffffffffu, ps, 2);
            lrow[hh] = lrow[hh] * corr + ps;
#pragma unroll
            for (int nt = 0; nt < 8; nt++) {
                acc[nt][hh * 2]     *= corr;
                acc[nt][hh * 2 + 1] *= corr;
            }
            mrow[hh] = nm;
        }

#pragma unroll
        for (int nt = 0; nt < 8; nt++) {
            Ps[(wm0 + g) * AST + nt * 8 + t4 * 2]         = f2tf32(s[nt][0]);
            Ps[(wm0 + g) * AST + nt * 8 + t4 * 2 + 1]     = f2tf32(s[nt][1]);
            Ps[(wm0 + g + 8) * AST + nt * 8 + t4 * 2]     = f2tf32(s[nt][2]);
            Ps[(wm0 + g + 8) * AST + nt * 8 + t4 * 2 + 1] = f2tf32(s[nt][3]);
        }
        __syncwarp();

#pragma unroll
        for (int ks = 0; ks < 64; ks += 8) {
            const uint32_t a0 = Ps[(wm0 + g) * AST + ks + t4];
            const uint32_t a1 = Ps[(wm0 + g + 8) * AST + ks + t4];
            const uint32_t a2 = Ps[(wm0 + g) * AST + ks + 4 + t4];
            const uint32_t a3 = Ps[(wm0 + g + 8) * AST + ks + 4 + t4];
#pragma unroll
            for (int nt = 0; nt < 8; nt++) {
                const uint32_t b0 = Vs[(ks + t4) * VST + nt * 8 + g];
                const uint32_t b1 = Vs[(ks + 4 + t4) * VST + nt * 8 + g];
                mma_tf32(acc[nt], a0, a1, a2, a3, b0, b1);
            }
        }
    }

    const int b_ = bh >> 4;
    const int h_ = bh & 15;
    const float inv0 = 1.f / lrow[0];
    const float inv1 = 1.f / lrow[1];
#pragma unroll
    for (int hh = 0; hh < 2; hh++) {
        const int n_ = q0 + wm0 + g + hh * 8;
        const float inv = hh ? inv1 : inv0;
        float* orow = &o[((size_t)(b_ * NTOK + n_)) * DMODEL + h_ * HDIM];
#pragma unroll
        for (int nt = 0; nt < 8; nt++) {
            float2 ov;
            ov.x = acc[nt][hh * 2] * inv;
            ov.y = acc[nt][hh * 2 + 1] * inv;
            *(float2*)&orow[nt * 8 + t4 * 2] = ov;
        }
    }
}

// ---------------------------------------------------------------------------
extern "C" void kernel_launch(void* const* d_in, const int* in_sizes, int n_in,
                              void* d_out, int out_size)
{
    const float* x  = (const float*)d_in[0];
    const float* Wq = (const float*)d_in[1];
    const float* bq = (const float*)d_in[2];
    const float* Wk = (const float*)d_in[3];
    const float* bk = (const float*)d_in[4];
    const float* Wv = (const float*)d_in[5];
    const float* bv = (const float*)d_in[6];
    const float* Wo = (const float*)d_in[7];
    const float* bo = (const float*)d_in[8];
    float* out = (float*)d_out;

    float *gq, *gk, *gv, *ga;
    cudaGetSymbolAddress((void**)&gq, g_q);
    cudaGetSymbolAddress((void**)&gk, g_k);
    cudaGetSymbolAddress((void**)&gv, g_v);
    cudaGetSymbolAddress((void**)&ga, g_attn);

    const float qscale = 0.125f;  // 1/sqrt(64)

    dim3 gqkv(DMODEL / 128, MROWS / 128, 3);
    gemm_tf32_kernel<<<gqkv, 128>>>(x,
                                    Wq, bq, gq,
                                    Wk, bk, gk,
                                    Wv, bv, gv,
                                    1, qscale);

    const int attn_smem = ATTN_SMEM_WORDS * sizeof(uint32_t);  // ~105.5 KB
    cudaFuncSetAttribute(attn_tc_kernel,
                         cudaFuncAttributeMaxDynamicSharedMemorySize, attn_smem);
    dim3 gattn(NTOK / 128, BATCH * NHEAD);   // (16, 64)
    attn_tc_kernel<<<gattn, 256, attn_smem>>>(gq, gk, gv, ga);

    dim3 ggemm(DMODEL / 128, MROWS / 128, 1);
    gemm_tf32_kernel<<<ggemm, 128>>>(ga,
                                     Wo, bo, out,
                                     nullptr, nullptr, nullptr,
                                     nullptr, nullptr, nullptr,
                                     0, 1.f);
}

// round 11
// speedup vs baseline: 4.3586x; 1.0452x over previous
#include <cuda_runtime.h>
#include <math.h>
#include <stdint.h>

#define BATCH 4
#define NTOK 2048
#define DMODEL 1024
#define NHEAD 16
#define HDIM 64
#define MROWS (BATCH * NTOK)   // 8192

__device__ float g_q[BATCH * NHEAD * NTOK * HDIM];     // [B,H,N,hd]
__device__ float g_k[BATCH * NHEAD * NTOK * HDIM];
__device__ float g_v[BATCH * NHEAD * NTOK * HDIM];
__device__ float g_attn[MROWS * DMODEL];               // [B*N, D]

__device__ __forceinline__ uint32_t f2tf32(float f) {
    uint32_t u;
    asm("cvt.rna.tf32.f32 %0, %1;" : "=r"(u) : "f"(f));
    return u;
}

__device__ __forceinline__ void mma_tf32(float c[4],
                                         uint32_t a0, uint32_t a1, uint32_t a2, uint32_t a3,
                                         uint32_t b0, uint32_t b1) {
    asm volatile(
        "mma.sync.aligned.m16n8k8.row.col.f32.tf32.tf32.f32 "
        "{%0,%1,%2,%3}, {%4,%5,%6,%7}, {%8,%9}, {%0,%1,%2,%3};\n"
        : "+f"(c[0]), "+f"(c[1]), "+f"(c[2]), "+f"(c[3])
        : "r"(a0), "r"(a1), "r"(a2), "r"(a3), "r"(b0), "r"(b1));
}

// ---------------------------------------------------------------------------
// TF32 tensor-core GEMM (unchanged from R7 winner).
// ---------------------------------------------------------------------------
#define AS_STRIDE 20
#define BS_STRIDE 136
#define AS_WORDS (128 * AS_STRIDE)
#define BS_WORDS (16 * BS_STRIDE)

__global__ __launch_bounds__(128, 2)
void gemm_tf32_kernel(const float* __restrict__ A,
                      const float* __restrict__ W0,
                      const float* __restrict__ b0p,
                      float* __restrict__ C0,
                      const float* __restrict__ W1,
                      const float* __restrict__ b1p,
                      float* __restrict__ C1,
                      const float* __restrict__ W2,
                      const float* __restrict__ b2p,
                      float* __restrict__ C2,
                      int head_layout, float scale0)
{
    __shared__ uint32_t As[2 * AS_WORDS];
    __shared__ uint32_t Bs[2 * BS_WORDS];

    const int z = blockIdx.z;
    const float* W    = (z == 0) ? W0 : (z == 1) ? W1 : W2;
    const float* bias = (z == 0) ? b0p : (z == 1) ? b1p : b2p;
    float* C          = (z == 0) ? C0 : (z == 1) ? C1 : C2;
    const float scale = (z == 0) ? scale0 : 1.f;

    const int t     = threadIdx.x;
    const int warp  = t >> 5;
    const int lane  = t & 31;
    const int g     = lane >> 2;
    const int tid4  = lane & 3;
    const int wm0   = (warp >> 1) * 64;
    const int wn0   = (warp & 1) * 64;

    const int m0 = blockIdx.y * 128;
    const int n0 = blockIdx.x * 128;

    const int ar0 = t >> 2;
    const int ac4 = t & 3;
    const int br0 = t >> 5;
    const int bc4 = t & 31;

    const float* pa = A + (size_t)(m0 + ar0) * 1024 + ac4 * 4;
    const float* pb = W + (size_t)br0 * 1024 + n0 + bc4 * 4;

    float4 av[4], bv[4];
#pragma unroll
    for (int r = 0; r < 4; r++) {
        av[r] = *(const float4*)(pa + (size_t)(r * 32) * 1024);
        bv[r] = *(const float4*)(pb + (size_t)(r * 4) * 1024);
    }
#pragma unroll
    for (int r = 0; r < 4; r++) {
        uint32_t* p = &As[(ar0 + r * 32) * AS_STRIDE + ac4 * 4];
        p[0] = f2tf32(av[r].x); p[1] = f2tf32(av[r].y);
        p[2] = f2tf32(av[r].z); p[3] = f2tf32(av[r].w);
        uint32_t* q = &Bs[(br0 + r * 4) * BS_STRIDE + bc4 * 4];
        q[0] = f2tf32(bv[r].x); q[1] = f2tf32(bv[r].y);
        q[2] = f2tf32(bv[r].z); q[3] = f2tf32(bv[r].w);
    }
    __syncthreads();

    float acc[4][8][4] = {};
    int cur = 0;

    for (int k0 = 0; k0 < 1024; k0 += 16) {
        const bool has_next = (k0 + 16 < 1024);
        if (has_next) {
#pragma unroll
            for (int r = 0; r < 4; r++) {
                av[r] = *(const float4*)(pa + (size_t)(r * 32) * 1024 + k0 + 16);
                bv[r] = *(const float4*)(pb + (size_t)(r * 4 + k0 + 16) * 1024);
            }
        }

        const uint32_t* Ac = &As[cur * AS_WORDS];
        const uint32_t* Bc = &Bs[cur * BS_WORDS];
#pragma unroll
        for (int ks = 0; ks < 16; ks += 8) {
            uint32_t afr[4][4];
            uint32_t bfr[8][2];
#pragma unroll
            for (int mi = 0; mi < 4; mi++) {
                const int r0 = wm0 + mi * 16 + g;
                afr[mi][0] = Ac[r0 * AS_STRIDE + ks + tid4];
                afr[mi][1] = Ac[(r0 + 8) * AS_STRIDE + ks + tid4];
                afr[mi][2] = Ac[r0 * AS_STRIDE + ks + 4 + tid4];
                afr[mi][3] = Ac[(r0 + 8) * AS_STRIDE + ks + 4 + tid4];
            }
#pragma unroll
            for (int ni = 0; ni < 8; ni++) {
                const int c = wn0 + ni * 8 + g;
                bfr[ni][0] = Bc[(ks + tid4) * BS_STRIDE + c];
                bfr[ni][1] = Bc[(ks + 4 + tid4) * BS_STRIDE + c];
            }
#pragma unroll
            for (int mi = 0; mi < 4; mi++)
#pragma unroll
                for (int ni = 0; ni < 8; ni++)
                    mma_tf32(acc[mi][ni], afr[mi][0], afr[mi][1], afr[mi][2], afr[mi][3],
                             bfr[ni][0], bfr[ni][1]);
        }

        if (has_next) {
            uint32_t* An = &As[(cur ^ 1) * AS_WORDS];
            uint32_t* Bn = &Bs[(cur ^ 1) * BS_WORDS];
#pragma unroll
            for (int r = 0; r < 4; r++) {
                uint32_t* p = &An[(ar0 + r * 32) * AS_STRIDE + ac4 * 4];
                p[0] = f2tf32(av[r].x); p[1] = f2tf32(av[r].y);
                p[2] = f2tf32(av[r].z); p[3] = f2tf32(av[r].w);
                uint32_t* q = &Bn[(br0 + r * 4) * BS_STRIDE + bc4 * 4];
                q[0] = f2tf32(bv[r].x); q[1] = f2tf32(bv[r].y);
                q[2] = f2tf32(bv[r].z); q[3] = f2tf32(bv[r].w);
            }
            __syncthreads();
        }
        cur ^= 1;
    }

#pragma unroll
    for (int ni = 0; ni < 8; ni++) {
        const int c = n0 + wn0 + ni * 8 + tid4 * 2;
        const float b0 = bias[c], b1 = bias[c + 1];
#pragma unroll
        for (int mi = 0; mi < 4; mi++) {
#pragma unroll
            for (int half = 0; half < 2; half++) {
                const int m = m0 + wm0 + mi * 16 + g + half * 8;
                float2 o;
                o.x = (acc[mi][ni][half * 2 + 0] + b0) * scale;
                o.y = (acc[mi][ni][half * 2 + 1] + b1) * scale;
                if (head_layout) {
                    const int b_  = m >> 11;
                    const int n_  = m & 2047;
                    const int h_  = c >> 6;
                    const int hd_ = c & 63;
                    *(float2*)&C[(((size_t)(b_ * NHEAD + h_) * NTOK) + n_) * HDIM + hd_] = o;
                } else {
                    *(float2*)&C[(size_t)m * 1024 + c] = o;
                }
            }
        }
    }
}

// ---------------------------------------------------------------------------
// Tensor-core flash attention (causal, tf32), R7 rework:
// 128 threads = 4 warps, warp tile 32x64 (mi=2), register-prefetched K/V.
// smem: Qs [128][68] | Ks [64][68] | Vs [64][72] | Ps [128][68]
// ---------------------------------------------------------------------------
#define AST 68
#define VST 72
#define SM_Q 0
#define SM_K (128 * AST)
#define SM_V (SM_K + 64 * AST)
#define SM_P (SM_V + 64 * VST)
#define ATTN_SMEM_WORDS (SM_P + 128 * AST)

__global__ __launch_bounds__(128, 2)
void attn_tc_kernel(const float* __restrict__ q,
                    const float* __restrict__ k,
                    const float* __restrict__ v,
                    float* __restrict__ o)
{
    extern __shared__ uint32_t sm[];
    uint32_t* Qs = sm + SM_Q;
    uint32_t* Ks = sm + SM_K;
    uint32_t* Vs = sm + SM_V;
    uint32_t* Ps = sm + SM_P;

    const int t    = threadIdx.x;
    const int warp = t >> 5;
    const int lane = t & 31;
    const int g    = lane >> 2;
    const int t4   = lane & 3;
    const int wm0  = warp * 32;        // warp covers 32 query rows

    const int qt = blockIdx.x;
    const int bh = blockIdx.y;
    const int q0 = qt * 128;

    const float* qp = q + (size_t)bh * NTOK * HDIM;
    const float* kp = k + (size_t)bh * NTOK * HDIM;
    const float* vp = v + (size_t)bh * NTOK * HDIM;

    // K/V tile load coordinates: 64 rows x 16 float4 = 1024 / 128 thr = 8 iters
    const int lrow = t >> 4;           // base row 0..7 (+8*i)
    const int lc4  = t & 15;

    // Load Q tile [128][64]: 2048 float4 / 128 = 16 iters
#pragma unroll
    for (int i = 0; i < 16; i++) {
        const int idx = t + i * 128;
        const int row = idx >> 4;
        const int c4  = idx & 15;
        float4 qv = *(const float4*)&qp[(size_t)(q0 + row) * HDIM + c4 * 4];
        uint32_t* p = &Qs[row * AST + c4 * 4];
        p[0] = f2tf32(qv.x); p[1] = f2tf32(qv.y);
        p[2] = f2tf32(qv.z); p[3] = f2tf32(qv.w);
    }

    // Prefetch kt=0 K/V into registers
    float4 kreg[8], vreg[8];
#pragma unroll
    for (int i = 0; i < 8; i++) {
        const int row = lrow + i * 8;
        kreg[i] = *(const float4*)&kp[(size_t)row * HDIM + lc4 * 4];
        vreg[i] = *(const float4*)&vp[(size_t)row * HDIM + lc4 * 4];
    }

    float acc[2][8][4] = {};
    float mrow[2][2] = {{-INFINITY, -INFINITY}, {-INFINITY, -INFINITY}};
    float lrw[2][2]  = {{0.f, 0.f}, {0.f, 0.f}};

    const int ktmax = 2 * qt + 1;
    for (int kt = 0; kt <= ktmax; kt++) {
        const int k0 = kt * 64;
        __syncthreads();   // previous iteration's K/V/P smem reads complete
        // publish prefetched K/V
#pragma unroll
        for (int i = 0; i < 8; i++) {
            const int row = lrow + i * 8;
            uint32_t* pk = &Ks[row * AST + lc4 * 4];
            pk[0] = f2tf32(kreg[i].x); pk[1] = f2tf32(kreg[i].y);
            pk[2] = f2tf32(kreg[i].z); pk[3] = f2tf32(kreg[i].w);
            uint32_t* pv = &Vs[row * VST + lc4 * 4];
            pv[0] = f2tf32(vreg[i].x); pv[1] = f2tf32(vreg[i].y);
            pv[2] = f2tf32(vreg[i].z); pv[3] = f2tf32(vreg[i].w);
        }
        __syncthreads();

        // prefetch next K/V tile (latency hides under compute below)
        if (kt < ktmax) {
            const int nk0 = k0 + 64;
#pragma unroll
            for (int i = 0; i < 8; i++) {
                const int row = nk0 + lrow + i * 8;
                kreg[i] = *(const float4*)&kp[(size_t)row * HDIM + lc4 * 4];
                vreg[i] = *(const float4*)&vp[(size_t)row * HDIM + lc4 * 4];
            }
        }

        // S = Q K^T  (mi=2 m-tiles, 8 n-tiles)
        float s[2][8][4] = {};
#pragma unroll
        for (int ks = 0; ks < 64; ks += 8) {
            uint32_t a[2][4];
#pragma unroll
            for (int mi = 0; mi < 2; mi++) {
                const int r0 = wm0 + mi * 16 + g;
                a[mi][0] = Qs[r0 * AST + ks + t4];
                a[mi][1] = Qs[(r0 + 8) * AST + ks + t4];
                a[mi][2] = Qs[r0 * AST + ks + 4 + t4];
                a[mi][3] = Qs[(r0 + 8) * AST + ks + 4 + t4];
            }
#pragma unroll
            for (int nt = 0; nt < 8; nt++) {
                const uint32_t b0 = Ks[(nt * 8 + g) * AST + ks + t4];
                const uint32_t b1 = Ks[(nt * 8 + g) * AST + ks + 4 + t4];
#pragma unroll
                for (int mi = 0; mi < 2; mi++)
                    mma_tf32(s[mi][nt], a[mi][0], a[mi][1], a[mi][2], a[mi][3], b0, b1);
            }
        }

        // Causal mask
        if (kt >= 2 * qt) {
#pragma unroll
            for (int mi = 0; mi < 2; mi++)
#pragma unroll
                for (int nt = 0; nt < 8; nt++)
#pragma unroll
                    for (int hh = 0; hh < 2; hh++)
#pragma unroll
                        for (int cc = 0; cc < 2; cc++) {
                            const int row = q0 + wm0 + mi * 16 + g + hh * 8;
                            const int col = k0 + nt * 8 + t4 * 2 + cc;
                            if (col > row) s[mi][nt][hh * 2 + cc] = -1e30f;
                        }
        }

        // Online softmax (rows wm0+mi*16+g+hh*8; reduce across t4 lanes)
#pragma unroll
        for (int mi = 0; mi < 2; mi++)
#pragma unroll
            for (int hh = 0; hh < 2; hh++) {
                float mx = -INFINITY;
#pragma unroll
                for (int nt = 0; nt < 8; nt++)
                    mx = fmaxf(mx, fmaxf(s[mi][nt][hh * 2], s[mi][nt][hh * 2 + 1]));
                mx = fmaxf(mx, __shfl_xor_sync(0xffffffffu, mx, 1));
                mx = fmaxf(mx, __shfl_xor_sync(0xffffffffu, mx, 2));
                const float nm = fmaxf(mrow[mi][hh], mx);
                const float corr = __expf(mrow[mi][hh] - nm);
                float ps = 0.f;
#pragma unroll
                for (int nt = 0; nt < 8; nt++) {
                    s[mi][nt][hh * 2]     = __expf(s[mi][nt][hh * 2] - nm);
                    s[mi][nt][hh * 2 + 1] = __expf(s[mi][nt][hh * 2 + 1] - nm);
                    ps += s[mi][nt][hh * 2] + s[mi][nt][hh * 2 + 1];
                }
                ps += __shfl_xor_sync(0xffffffffu, ps, 1);
                ps += __shfl_xor_sync(0xffffffffu, ps, 2);
                lrw[mi][hh] = lrw[mi][hh] * corr + ps;
#pragma unroll
                for (int nt = 0; nt < 8; nt++) {
                    acc[mi][nt][hh * 2]     *= corr;
                    acc[mi][nt][hh * 2 + 1] *= corr;
                }
                mrow[mi][hh] = nm;
            }

        // P -> smem (warp-private rows wm0..wm0+31)
#pragma unroll
        for (int mi = 0; mi < 2; mi++)
#pragma unroll
            for (int nt = 0; nt < 8; nt++) {
                const int r0 = wm0 + mi * 16 + g;
                Ps[r0 * AST + nt * 8 + t4 * 2]           = f2tf32(s[mi][nt][0]);
                Ps[r0 * AST + nt * 8 + t4 * 2 + 1]       = f2tf32(s[mi][nt][1]);
                Ps[(r0 + 8) * AST + nt * 8 + t4 * 2]     = f2tf32(s[mi][nt][2]);
                Ps[(r0 + 8) * AST + nt * 8 + t4 * 2 + 1] = f2tf32(s[mi][nt][3]);
            }
        __syncwarp();

        // O += P V
#pragma unroll
        for (int ks = 0; ks < 64; ks += 8) {
            uint32_t a[2][4];
#pragma unroll
            for (int mi = 0; mi < 2; mi++) {
                const int r0 = wm0 + mi * 16 + g;
                a[mi][0] = Ps[r0 * AST + ks + t4];
                a[mi][1] = Ps[(r0 + 8) * AST + ks + t4];
                a[mi][2] = Ps[r0 * AST + ks + 4 + t4];
                a[mi][3] = Ps[(r0 + 8) * AST + ks + 4 + t4];
            }
#pragma unroll
            for (int nt = 0; nt < 8; nt++) {
                const uint32_t b0 = Vs[(ks + t4) * VST + nt * 8 + g];
                const uint32_t b1 = Vs[(ks + 4 + t4) * VST + nt * 8 + g];
#pragma unroll
                for (int mi = 0; mi < 2; mi++)
                    mma_tf32(acc[mi][nt], a[mi][0], a[mi][1], a[mi][2], a[mi][3], b0, b1);
            }
        }
    }

    // Epilogue
    const int b_ = bh >> 4;
    const int h_ = bh & 15;
#pragma unroll
    for (int mi = 0; mi < 2; mi++)
#pragma unroll
        for (int hh = 0; hh < 2; hh++) {
            const int n_ = q0 + wm0 + mi * 16 + g + hh * 8;
            const float inv = 1.f / lrw[mi][hh];
            float* orow = &o[((size_t)(b_ * NTOK + n_)) * DMODEL + h_ * HDIM];
#pragma unroll
            for (int nt = 0; nt < 8; nt++) {
                float2 ov;
                ov.x = acc[mi][nt][hh * 2] * inv;
                ov.y = acc[mi][nt][hh * 2 + 1] * inv;
                *(float2*)&orow[nt * 8 + t4 * 2] = ov;
            }
        }
}

// ---------------------------------------------------------------------------
extern "C" void kernel_launch(void* const* d_in, const int* in_sizes, int n_in,
                              void* d_out, int out_size)
{
    const float* x  = (const float*)d_in[0];
    const float* Wq = (const float*)d_in[1];
    const float* bq = (const float*)d_in[2];
    const float* Wk = (const float*)d_in[3];
    const float* bk = (const float*)d_in[4];
    const float* Wv = (const float*)d_in[5];
    const float* bv = (const float*)d_in[6];
    const float* Wo = (const float*)d_in[7];
    const float* bo = (const float*)d_in[8];
    float* out = (float*)d_out;

    float *gq, *gk, *gv, *ga;
    cudaGetSymbolAddress((void**)&gq, g_q);
    cudaGetSymbolAddress((void**)&gk, g_k);
    cudaGetSymbolAddress((void**)&gv, g_v);
    cudaGetSymbolAddress((void**)&ga, g_attn);

    const float qscale = 0.125f;  // 1/sqrt(64)

    dim3 gqkv(DMODEL / 128, MROWS / 128, 3);
    gemm_tf32_kernel<<<gqkv, 128>>>(x,
                                    Wq, bq, gq,
                                    Wk, bk, gk,
                                    Wv, bv, gv,
                                    1, qscale);

    const int attn_smem = ATTN_SMEM_WORDS * sizeof(uint32_t);  // ~105.5 KB
    cudaFuncSetAttribute(attn_tc_kernel,
                         cudaFuncAttributeMaxDynamicSharedMemorySize, attn_smem);
    dim3 gattn(NTOK / 128, BATCH * NHEAD);   // (16, 64)
    attn_tc_kernel<<<gattn, 128, attn_smem>>>(gq, gk, gv, ga);

    dim3 ggemm(DMODEL / 128, MROWS / 128, 1);
    gemm_tf32_kernel<<<ggemm, 128>>>(ga,
                                     Wo, bo, out,
                                     nullptr, nullptr, nullptr,
                                     nullptr, nullptr, nullptr,
                                     0, 1.f);
}